// round 1
// baseline (speedup 1.0000x reference)
#include <cuda_runtime.h>
#include <math.h>

#define BB   2
#define SS   2048
#define HID  1024
#define NH   16
#define DK   64
#define MM   (BB*SS)
#define MW   (SS/32)   // mask words per row

// ---------------- scratch (device globals; no allocations allowed) ----------
__device__ float    g_Qh[BB*NH*SS*DK];   // [b,h,s,d]
__device__ float    g_Kh[BB*NH*SS*DK];
__device__ float    g_Vh[BB*NH*SS*DK];
__device__ float    g_X [MM*HID];        // attention output, [b*s, h*d]
__device__ unsigned g_mb[BB*SS*MW];      // bit-packed mask

// ---------------- mask bit-pack ---------------------------------------------
__global__ __launch_bounds__(256)
void pack_mask_kernel(const int* __restrict__ mask, unsigned* __restrict__ out)
{
    int idx = blockIdx.x * blockDim.x + threadIdx.x;
    if (idx >= BB*SS*MW) return;
    int w = idx % MW;
    int q = (idx / MW) % SS;
    int b = idx / (SS*MW);
    const int* row = mask + ((long)b*SS + q)*SS + (long)w*32;
    unsigned bits = 0;
#pragma unroll
    for (int i = 0; i < 32; i++)
        bits |= (row[i] != 0) ? (1u << i) : 0u;
    out[idx] = bits;
}

// ---------------- GEMM + bias ------------------------------------------------
// C[M,N] = A[M,K] @ W[K,N] + bias[N]
// MODE 0: plain row-major [M,N] output
// MODE 1: head-split output [b, h, s, d]  (b=m>>11, s=m&2047, h=n>>6, d=n&63)
// Tiles: 128x128x8, 256 threads, 8x8 per-thread microtile.
template<int MODE>
__global__ __launch_bounds__(256)
void gemm_bias_kernel(const float* __restrict__ A, const float* __restrict__ W,
                      const float* __restrict__ bias, float* __restrict__ C)
{
    __shared__ float As[8][128];   // [k][m] (transposed)
    __shared__ float Bs[8][128];   // [k][n]

    const int t  = threadIdx.x;
    const int tx = t & 15;
    const int ty = t >> 4;
    const int m0 = blockIdx.y * 128;
    const int n0 = blockIdx.x * 128;

    const int arow  = t >> 1;         // 0..127
    const int akcol = (t & 1) * 4;    // 0 or 4
    const int bkrow = t >> 5;         // 0..7
    const int bcol  = (t & 31) * 4;   // 0..124

    float acc[8][8];
#pragma unroll
    for (int i = 0; i < 8; i++)
#pragma unroll
        for (int j = 0; j < 8; j++) acc[i][j] = 0.f;

    for (int k0 = 0; k0 < HID; k0 += 8) {
        float4 av = *reinterpret_cast<const float4*>(A + (long)(m0 + arow)*HID + k0 + akcol);
        As[akcol+0][arow] = av.x;
        As[akcol+1][arow] = av.y;
        As[akcol+2][arow] = av.z;
        As[akcol+3][arow] = av.w;
        float4 bv = *reinterpret_cast<const float4*>(W + (long)(k0 + bkrow)*HID + n0 + bcol);
        *reinterpret_cast<float4*>(&Bs[bkrow][bcol]) = bv;
        __syncthreads();

#pragma unroll
        for (int kk = 0; kk < 8; kk++) {
            float a[8], b[8];
#pragma unroll
            for (int i = 0; i < 8; i++) a[i] = As[kk][ty*8 + i];
#pragma unroll
            for (int j = 0; j < 8; j++) b[j] = Bs[kk][tx*8 + j];
#pragma unroll
            for (int i = 0; i < 8; i++)
#pragma unroll
                for (int j = 0; j < 8; j++) acc[i][j] += a[i] * b[j];
        }
        __syncthreads();
    }

#pragma unroll
    for (int i = 0; i < 8; i++) {
        const int m = m0 + ty*8 + i;
        const int b = m >> 11, s = m & 2047;
#pragma unroll
        for (int j = 0; j < 8; j++) {
            const int n = n0 + tx*8 + j;
            const float v = acc[i][j] + bias[n];
            if (MODE == 0) {
                C[(long)m*HID + n] = v;
            } else {
                const int h = n >> 6, d = n & 63;
                C[((long)((b*NH + h)*SS + s))*DK + d] = v;
            }
        }
    }
}

// ---------------- flash attention -------------------------------------------
// One CTA handles a 64-row Q tile for one (b,h). 256 threads as 16x16 grid,
// each thread owns a 4(q) x 4(k or d) microtile.
#define ATT_SMEM (4*64*65*4)

__global__ __launch_bounds__(256)
void flash_attn_kernel(const float* __restrict__ Qh, const float* __restrict__ Kh,
                       const float* __restrict__ Vh, const unsigned* __restrict__ maskb,
                       float* __restrict__ X)
{
    extern __shared__ float sm[];
    float* Qs = sm;             // [q][d]  64x65
    float* Ks = Qs + 64*65;     // [d][k]  64x65 (K transposed)
    float* Vs = Ks + 64*65;     // [k][d]  64x65
    float* Ps = Vs + 64*65;     // [q][k]  64x65

    const int t  = threadIdx.x;
    const int tx = t & 15;
    const int ty = t >> 4;
    const int qt = blockIdx.x;     // 0..31
    const int bh = blockIdx.y;     // 0..31
    const int b  = bh >> 4;
    const int h  = bh & 15;

    // load Q tile
    const float* Qbase = Qh + ((long)bh*SS + qt*64) * DK;
    for (int u = t; u < 64*64; u += 256) {
        int r = u >> 6, d = u & 63;
        Qs[r*65 + d] = Qbase[u];
    }

    float m_i[4], l_i[4], acc[4][4];
#pragma unroll
    for (int i = 0; i < 4; i++) {
        m_i[i] = -1e30f; l_i[i] = 0.f;
#pragma unroll
        for (int j = 0; j < 4; j++) acc[i][j] = 0.f;
    }

    const unsigned* mrow = maskb + ((long)b*SS + qt*64) * MW;
    const float scale = 0.125f;   // 1/sqrt(64)

    for (int kt = 0; kt < SS/64; kt++) {
        __syncthreads();   // previous iteration's PV done before overwriting K/V
        const float* Kbase = Kh + ((long)bh*SS + kt*64) * DK;
        const float* Vbase = Vh + ((long)bh*SS + kt*64) * DK;
        for (int u = t; u < 64*64; u += 256) {
            int kp = u >> 6, d = u & 63;
            Ks[d*65 + kp] = Kbase[u];
            Vs[kp*65 + d] = Vbase[u];
        }
        __syncthreads();

        // S = Q K^T (scaled later)
        float s[4][4];
#pragma unroll
        for (int i = 0; i < 4; i++)
#pragma unroll
            for (int j = 0; j < 4; j++) s[i][j] = 0.f;

#pragma unroll 4
        for (int d = 0; d < 64; d++) {
            float qv[4], kv[4];
#pragma unroll
            for (int i = 0; i < 4; i++) qv[i] = Qs[(ty*4 + i)*65 + d];
#pragma unroll
            for (int j = 0; j < 4; j++) kv[j] = Ks[d*65 + tx*4 + j];
#pragma unroll
            for (int i = 0; i < 4; i++)
#pragma unroll
                for (int j = 0; j < 4; j++) s[i][j] += qv[i] * kv[j];
        }

        // mask bits for this thread's 4x4 block
        unsigned mbits[4];
#pragma unroll
        for (int i = 0; i < 4; i++) {
            unsigned w = mrow[(ty*4 + i)*MW + kt*2 + (tx >> 3)];
            mbits[i] = (w >> ((tx*4) & 31)) & 0xFu;
        }

        // row max over unmasked entries
        float mloc[4];
#pragma unroll
        for (int i = 0; i < 4; i++) {
            float mv = -1e30f;
#pragma unroll
            for (int j = 0; j < 4; j++)
                if ((mbits[i] >> j) & 1) mv = fmaxf(mv, s[i][j] * scale);
            mloc[i] = mv;
        }
#pragma unroll
        for (int off = 1; off < 16; off <<= 1)
#pragma unroll
            for (int i = 0; i < 4; i++)
                mloc[i] = fmaxf(mloc[i], __shfl_xor_sync(0xffffffffu, mloc[i], off));

        float mnew[4], alpha[4];
#pragma unroll
        for (int i = 0; i < 4; i++) {
            mnew[i]  = fmaxf(m_i[i], mloc[i]);
            alpha[i] = __expf(m_i[i] - mnew[i]);
            m_i[i]   = mnew[i];
        }

        float p[4][4], rs[4];
#pragma unroll
        for (int i = 0; i < 4; i++) {
            rs[i] = 0.f;
#pragma unroll
            for (int j = 0; j < 4; j++) {
                float pv = ((mbits[i] >> j) & 1) ? __expf(s[i][j]*scale - mnew[i]) : 0.f;
                p[i][j] = pv;
                rs[i] += pv;
            }
        }
#pragma unroll
        for (int off = 1; off < 16; off <<= 1)
#pragma unroll
            for (int i = 0; i < 4; i++)
                rs[i] += __shfl_xor_sync(0xffffffffu, rs[i], off);

#pragma unroll
        for (int i = 0; i < 4; i++) {
            l_i[i] = l_i[i]*alpha[i] + rs[i];
#pragma unroll
            for (int j = 0; j < 4; j++) acc[i][j] *= alpha[i];
        }

        // publish P to smem, then PV
#pragma unroll
        for (int i = 0; i < 4; i++)
#pragma unroll
            for (int j = 0; j < 4; j++)
                Ps[(ty*4 + i)*65 + tx*4 + j] = p[i][j];
        __syncthreads();

#pragma unroll 4
        for (int kk = 0; kk < 64; kk++) {
            float pv[4], vv[4];
#pragma unroll
            for (int i = 0; i < 4; i++) pv[i] = Ps[(ty*4 + i)*65 + kk];
#pragma unroll
            for (int j = 0; j < 4; j++) vv[j] = Vs[kk*65 + tx*4 + j];
#pragma unroll
            for (int i = 0; i < 4; i++)
#pragma unroll
                for (int j = 0; j < 4; j++) acc[i][j] += pv[i] * vv[j];
        }
    }

    // epilogue: normalize and store to X[b*s, h*64 + d]
#pragma unroll
    for (int i = 0; i < 4; i++) {
        const float inv = (l_i[i] > 0.f) ? (1.f / l_i[i]) : 0.f;
        const long row = (long)(b*SS + qt*64 + ty*4 + i);
#pragma unroll
        for (int j = 0; j < 4; j++)
            X[row*HID + h*DK + tx*4 + j] = acc[i][j] * inv;
    }
}

// ---------------- launch -----------------------------------------------------
extern "C" void kernel_launch(void* const* d_in, const int* in_sizes, int n_in,
                              void* d_out, int out_size)
{
    const float* q    = (const float*)d_in[0];
    const float* k    = (const float*)d_in[1];
    const float* v    = (const float*)d_in[2];
    const int*   mask = (const int*)  d_in[3];
    const float* Wq   = (const float*)d_in[4];
    const float* bq   = (const float*)d_in[5];
    const float* Wk   = (const float*)d_in[6];
    const float* bk   = (const float*)d_in[7];
    const float* Wv   = (const float*)d_in[8];
    const float* bv   = (const float*)d_in[9];
    const float* Wo   = (const float*)d_in[10];
    const float* bo   = (const float*)d_in[11];
    float* out = (float*)d_out;

    float *Qh, *Kh, *Vh, *X; unsigned* mb;
    cudaGetSymbolAddress((void**)&Qh, g_Qh);
    cudaGetSymbolAddress((void**)&Kh, g_Kh);
    cudaGetSymbolAddress((void**)&Vh, g_Vh);
    cudaGetSymbolAddress((void**)&X,  g_X);
    cudaGetSymbolAddress((void**)&mb, g_mb);

    // 1) pack mask to bits
    pack_mask_kernel<<<(BB*SS*MW + 255)/256, 256>>>(mask, mb);

    // 2) Q/K/V projections (head-split output)
    dim3 gg(HID/128, MM/128);
    gemm_bias_kernel<1><<<gg, 256>>>(q, Wq, bq, Qh);
    gemm_bias_kernel<1><<<gg, 256>>>(k, Wk, bk, Kh);
    gemm_bias_kernel<1><<<gg, 256>>>(v, Wv, bv, Vh);

    // 3) flash attention
    cudaFuncSetAttribute(flash_attn_kernel,
                         cudaFuncAttributeMaxDynamicSharedMemorySize, ATT_SMEM);
    flash_attn_kernel<<<dim3(SS/64, BB*NH), 256, ATT_SMEM>>>(Qh, Kh, Vh, mb, X);

    // 4) output projection (plain layout into d_out)
    gemm_bias_kernel<0><<<gg, 256>>>(X, Wo, bo, out);
}

// round 3
// speedup vs baseline: 1.5085x; 1.5085x over previous
#include <cuda_runtime.h>
#include <cuda_bf16.h>
#include <math.h>
#include <stdint.h>

#define BB   2
#define SS   2048
#define HID  1024
#define NH   16
#define DK   64
#define MM   (BB*SS)
#define MW   (SS/32)

// ---------------- scratch (device globals; no allocations allowed) ----------
__device__ float          g_Qh[BB*NH*SS*DK];
__device__ float          g_Kh[BB*NH*SS*DK];
__device__ float          g_Vh[BB*NH*SS*DK];
__device__ float          g_X [MM*HID];
__device__ __nv_bfloat16  g_Whi[4*HID*HID];   // transposed weights hi plane [n][k]
__device__ __nv_bfloat16  g_Wlo[4*HID*HID];   // transposed weights lo plane
__device__ __nv_bfloat16  g_Ahi[MM*HID];      // activation hi plane (reused q,k,v,X)
__device__ __nv_bfloat16  g_Alo[MM*HID];
__device__ unsigned       g_mb[BB*SS*MW];

// ---------------- helpers ----------------------------------------------------
__device__ __forceinline__ uint32_t smem_u32(const void* p) {
    uint32_t a;
    asm("{ .reg .u64 t; cvta.to.shared.u64 t, %1; cvt.u32.u64 %0, t; }"
        : "=r"(a) : "l"(p));
    return a;
}
__device__ __forceinline__ uint32_t lds32(uint32_t a) {
    uint32_t v; asm volatile("ld.shared.b32 %0, [%1];" : "=r"(v) : "r"(a)); return v;
}
#define CPA(dst, src) \
    asm volatile("cp.async.ca.shared.global [%0], [%1], 16;" :: "r"(dst), "l"(src))
#define MMA_BF16(c, a, b0, b1) \
    asm volatile("mma.sync.aligned.m16n8k16.row.col.f32.bf16.bf16.f32 " \
                 "{%0,%1,%2,%3},{%4,%5,%6,%7},{%8,%9},{%0,%1,%2,%3};" \
                 : "+f"((c)[0]), "+f"((c)[1]), "+f"((c)[2]), "+f"((c)[3]) \
                 : "r"((a)[0]), "r"((a)[1]), "r"((a)[2]), "r"((a)[3]), \
                   "r"(b0), "r"(b1))

__device__ __forceinline__ void split_bf16(float x, __nv_bfloat16& h, __nv_bfloat16& l) {
    h = __float2bfloat16(x);
    l = __float2bfloat16(x - __bfloat162float(h));
}

// ---------------- mask bit-pack ---------------------------------------------
__global__ __launch_bounds__(256)
void pack_mask_kernel(const int* __restrict__ mask, unsigned* __restrict__ out)
{
    int idx = blockIdx.x * blockDim.x + threadIdx.x;
    if (idx >= BB*SS*MW) return;
    int w = idx % MW;
    int q = (idx / MW) % SS;
    int b = idx / (SS*MW);
    const int* row = mask + ((long)b*SS + q)*SS + (long)w*32;
    unsigned bits = 0;
#pragma unroll
    for (int i = 0; i < 32; i++)
        bits |= (row[i] != 0) ? (1u << i) : 0u;
    out[idx] = bits;
}

// ---------------- weight transpose + bf16 split ------------------------------
// Thi/Tlo[n][k] = split(W[k][n])
__global__ __launch_bounds__(256)
void transpose_split_kernel(const float* __restrict__ W,
                            __nv_bfloat16* __restrict__ Thi,
                            __nv_bfloat16* __restrict__ Tlo)
{
    __shared__ float tile[32][33];
    const int tx = threadIdx.x & 31, ty = threadIdx.x >> 5;
    const int nb = blockIdx.x * 32, kb = blockIdx.y * 32;
#pragma unroll
    for (int i = 0; i < 32; i += 8)
        tile[ty + i][tx] = W[(long)(kb + ty + i)*HID + nb + tx];
    __syncthreads();
#pragma unroll
    for (int i = 0; i < 32; i += 8) {
        float x = tile[tx][ty + i];
        __nv_bfloat16 h, l; split_bf16(x, h, l);
        Thi[(long)(nb + ty + i)*HID + kb + tx] = h;
        Tlo[(long)(nb + ty + i)*HID + kb + tx] = l;
    }
}

// ---------------- elementwise bf16 split -------------------------------------
__global__ __launch_bounds__(256)
void convert_split_kernel(const float* __restrict__ x,
                          __nv_bfloat16* __restrict__ hi,
                          __nv_bfloat16* __restrict__ lo, int n4)
{
    int i = blockIdx.x * blockDim.x + threadIdx.x;
    if (i >= n4) return;
    float4 v = reinterpret_cast<const float4*>(x)[i];
    __nv_bfloat16 h0,h1,h2,h3,l0,l1,l2,l3;
    split_bf16(v.x, h0, l0); split_bf16(v.y, h1, l1);
    split_bf16(v.z, h2, l2); split_bf16(v.w, h3, l3);
    uint2 ph, pl;
    ph.x = (uint32_t)__bfloat16_as_ushort(h0) | ((uint32_t)__bfloat16_as_ushort(h1) << 16);
    ph.y = (uint32_t)__bfloat16_as_ushort(h2) | ((uint32_t)__bfloat16_as_ushort(h3) << 16);
    pl.x = (uint32_t)__bfloat16_as_ushort(l0) | ((uint32_t)__bfloat16_as_ushort(l1) << 16);
    pl.y = (uint32_t)__bfloat16_as_ushort(l2) | ((uint32_t)__bfloat16_as_ushort(l3) << 16);
    reinterpret_cast<uint2*>(hi)[i] = ph;
    reinterpret_cast<uint2*>(lo)[i] = pl;
}

// ---------------- bf16-split mma GEMM + bias ---------------------------------
// C[M,N] = A[M,K] @ W[K,N] + bias, A/B given as bf16 hi/lo planes,
// B planes K-major per N row ([n][k]).  CTA 128x128, 8 warps (4m x 2n),
// warp tile 32x64, mma m16n8k16, 3 passes (hh, hl, lh).
#define LDK   40              // padded smem row length in bf16 elems (80 B)
#define PS    (128*LDK*2)     // plane bytes = 10240
#define BS    (4*PS)          // buffer bytes = 40960
#define GEMM_SMEM (2*BS)      // 81920
#define NCHUNK (HID/32)

template<int MODE>
__global__ __launch_bounds__(256, 1)
void gemm_mma_kernel(const __nv_bfloat16* __restrict__ Ahi,
                     const __nv_bfloat16* __restrict__ Alo,
                     const __nv_bfloat16* __restrict__ Bhi,
                     const __nv_bfloat16* __restrict__ Blo,
                     const float* __restrict__ bias, float* __restrict__ C)
{
    extern __shared__ char smem[];
    const uint32_t sb = smem_u32(smem);
    const int t = threadIdx.x, lane = t & 31;
    const int w = t >> 5;
    const int warp_m = w & 3, warp_n = w >> 2;
    const int g = lane >> 2, tq = lane & 3;
    const int m0 = blockIdx.y * 128, n0 = blockIdx.x * 128;

    float acc[2][8][4];
#pragma unroll
    for (int mf = 0; mf < 2; mf++)
#pragma unroll
        for (int nf = 0; nf < 8; nf++)
#pragma unroll
            for (int r = 0; r < 4; r++) acc[mf][nf][r] = 0.f;

    auto issue = [&](int ck, int buf) {
        const long k0 = (long)ck * 32;
#pragma unroll
        for (int i = 0; i < 2; i++) {
            const int s = t + i*256;            // 0..511
            const int row = s >> 2;             // 0..127
            const int ks  = s & 3;              // 16B segment along k
            const uint32_t d = sb + buf*BS + row*(LDK*2) + ks*16;
            const long ao = (long)(m0 + row)*HID + k0 + ks*8;
            const long bo = (long)(n0 + row)*HID + k0 + ks*8;
            CPA(d + 0*PS, Ahi + ao);
            CPA(d + 1*PS, Alo + ao);
            CPA(d + 2*PS, Bhi + bo);
            CPA(d + 3*PS, Blo + bo);
        }
        asm volatile("cp.async.commit_group;" ::: "memory");
    };

    issue(0, 0);
    issue(1, 1);

    for (int ck = 0; ck < NCHUNK; ck++) {
        if (ck + 1 < NCHUNK) asm volatile("cp.async.wait_group 1;" ::: "memory");
        else                 asm volatile("cp.async.wait_group 0;" ::: "memory");
        __syncthreads();

        const uint32_t uA = sb + (ck & 1)*BS;
        const uint32_t uB = uA + 2*PS;
#pragma unroll
        for (int ks = 0; ks < 2; ks++) {
            const uint32_t acol = ks*32 + tq*4;     // byte offset along k
            uint32_t ah[2][4], al[2][4];
#pragma unroll
            for (int mf = 0; mf < 2; mf++) {
                const uint32_t r = uA + (warp_m*32 + mf*16 + g)*(LDK*2) + acol;
                ah[mf][0] = lds32(r);
                ah[mf][1] = lds32(r + 8*(LDK*2));
                ah[mf][2] = lds32(r + 16);
                ah[mf][3] = lds32(r + 8*(LDK*2) + 16);
                al[mf][0] = lds32(r + PS);
                al[mf][1] = lds32(r + PS + 8*(LDK*2));
                al[mf][2] = lds32(r + PS + 16);
                al[mf][3] = lds32(r + PS + 8*(LDK*2) + 16);
            }
#pragma unroll
            for (int nf = 0; nf < 8; nf++) {
                const uint32_t rb = uB + (warp_n*64 + nf*8 + g)*(LDK*2) + acol;
                const uint32_t bh0 = lds32(rb),      bh1 = lds32(rb + 16);
                const uint32_t bl0 = lds32(rb + PS), bl1 = lds32(rb + PS + 16);
#pragma unroll
                for (int mf = 0; mf < 2; mf++) {
                    MMA_BF16(acc[mf][nf], ah[mf], bh0, bh1);
                    MMA_BF16(acc[mf][nf], ah[mf], bl0, bl1);
                    MMA_BF16(acc[mf][nf], al[mf], bh0, bh1);
                }
            }
        }
        __syncthreads();
        if (ck + 2 < NCHUNK) issue(ck + 2, ck & 1);
    }

    // epilogue: registers -> gmem with bias
#pragma unroll
    for (int nf = 0; nf < 8; nf++) {
        const int cb = n0 + warp_n*64 + nf*8 + 2*tq;
        const float bx = bias[cb], by = bias[cb + 1];
#pragma unroll
        for (int mf = 0; mf < 2; mf++) {
#pragma unroll
            for (int half = 0; half < 2; half++) {
                const int m = m0 + warp_m*32 + mf*16 + g + half*8;
                float2 v;
                v.x = acc[mf][nf][half*2 + 0] + bx;
                v.y = acc[mf][nf][half*2 + 1] + by;
                if (MODE == 0) {
                    *reinterpret_cast<float2*>(C + (long)m*HID + cb) = v;
                } else {
                    const int b = m >> 11, s = m & 2047;
                    const int h = cb >> 6, d = cb & 63;
                    *reinterpret_cast<float2*>(
                        C + ((long)((b*NH + h)*SS + s))*DK + d) = v;
                }
            }
        }
    }
}

// ---------------- flash attention (fp32 SIMT, unchanged) ---------------------
#define ATT_SMEM (4*64*65*4)

__global__ __launch_bounds__(256)
void flash_attn_kernel(const float* __restrict__ Qh, const float* __restrict__ Kh,
                       const float* __restrict__ Vh, const unsigned* __restrict__ maskb,
                       float* __restrict__ X)
{
    extern __shared__ float sm[];
    float* Qs = sm;
    float* Ks = Qs + 64*65;
    float* Vs = Ks + 64*65;
    float* Ps = Vs + 64*65;

    const int t  = threadIdx.x;
    const int tx = t & 15;
    const int ty = t >> 4;
    const int qt = blockIdx.x;
    const int bh = blockIdx.y;
    const int b  = bh >> 4;
    const int h  = bh & 15;

    const float* Qbase = Qh + ((long)bh*SS + qt*64) * DK;
    for (int u = t; u < 64*64; u += 256) {
        int r = u >> 6, d = u & 63;
        Qs[r*65 + d] = Qbase[u];
    }

    float m_i[4], l_i[4], acc[4][4];
#pragma unroll
    for (int i = 0; i < 4; i++) {
        m_i[i] = -1e30f; l_i[i] = 0.f;
#pragma unroll
        for (int j = 0; j < 4; j++) acc[i][j] = 0.f;
    }

    const unsigned* mrow = maskb + ((long)b*SS + qt*64) * MW;
    const float scale = 0.125f;

    for (int kt = 0; kt < SS/64; kt++) {
        __syncthreads();
        const float* Kbase = Kh + ((long)bh*SS + kt*64) * DK;
        const float* Vbase = Vh + ((long)bh*SS + kt*64) * DK;
        for (int u = t; u < 64*64; u += 256) {
            int kp = u >> 6, d = u & 63;
            Ks[d*65 + kp] = Kbase[u];
            Vs[kp*65 + d] = Vbase[u];
        }
        __syncthreads();

        float s[4][4];
#pragma unroll
        for (int i = 0; i < 4; i++)
#pragma unroll
            for (int j = 0; j < 4; j++) s[i][j] = 0.f;

#pragma unroll 4
        for (int d = 0; d < 64; d++) {
            float qv[4], kv[4];
#pragma unroll
            for (int i = 0; i < 4; i++) qv[i] = Qs[(ty*4 + i)*65 + d];
#pragma unroll
            for (int j = 0; j < 4; j++) kv[j] = Ks[d*65 + tx*4 + j];
#pragma unroll
            for (int i = 0; i < 4; i++)
#pragma unroll
                for (int j = 0; j < 4; j++) s[i][j] += qv[i] * kv[j];
        }

        unsigned mbits[4];
#pragma unroll
        for (int i = 0; i < 4; i++) {
            unsigned w = mrow[(ty*4 + i)*MW + kt*2 + (tx >> 3)];
            mbits[i] = (w >> ((tx*4) & 31)) & 0xFu;
        }

        float mloc[4];
#pragma unroll
        for (int i = 0; i < 4; i++) {
            float mv = -1e30f;
#pragma unroll
            for (int j = 0; j < 4; j++)
                if ((mbits[i] >> j) & 1) mv = fmaxf(mv, s[i][j] * scale);
            mloc[i] = mv;
        }
#pragma unroll
        for (int off = 1; off < 16; off <<= 1)
#pragma unroll
            for (int i = 0; i < 4; i++)
                mloc[i] = fmaxf(mloc[i], __shfl_xor_sync(0xffffffffu, mloc[i], off));

        float mnew[4], alpha[4];
#pragma unroll
        for (int i = 0; i < 4; i++) {
            mnew[i]  = fmaxf(m_i[i], mloc[i]);
            alpha[i] = __expf(m_i[i] - mnew[i]);
            m_i[i]   = mnew[i];
        }

        float p[4][4], rs[4];
#pragma unroll
        for (int i = 0; i < 4; i++) {
            rs[i] = 0.f;
#pragma unroll
            for (int j = 0; j < 4; j++) {
                float pv = ((mbits[i] >> j) & 1) ? __expf(s[i][j]*scale - mnew[i]) : 0.f;
                p[i][j] = pv;
                rs[i] += pv;
            }
        }
#pragma unroll
        for (int off = 1; off < 16; off <<= 1)
#pragma unroll
            for (int i = 0; i < 4; i++)
                rs[i] += __shfl_xor_sync(0xffffffffu, rs[i], off);

#pragma unroll
        for (int i = 0; i < 4; i++) {
            l_i[i] = l_i[i]*alpha[i] + rs[i];
#pragma unroll
            for (int j = 0; j < 4; j++) acc[i][j] *= alpha[i];
        }

#pragma unroll
        for (int i = 0; i < 4; i++)
#pragma unroll
            for (int j = 0; j < 4; j++)
                Ps[(ty*4 + i)*65 + tx*4 + j] = p[i][j];
        __syncthreads();

#pragma unroll 4
        for (int kk = 0; kk < 64; kk++) {
            float pv[4], vv[4];
#pragma unroll
            for (int i = 0; i < 4; i++) pv[i] = Ps[(ty*4 + i)*65 + kk];
#pragma unroll
            for (int j = 0; j < 4; j++) vv[j] = Vs[kk*65 + tx*4 + j];
#pragma unroll
            for (int i = 0; i < 4; i++)
#pragma unroll
                for (int j = 0; j < 4; j++) acc[i][j] += pv[i] * vv[j];
        }
    }

#pragma unroll
    for (int i = 0; i < 4; i++) {
        const float inv = (l_i[i] > 0.f) ? (1.f / l_i[i]) : 0.f;
        const long row = (long)(b*SS + qt*64 + ty*4 + i);
#pragma unroll
        for (int j = 0; j < 4; j++)
            X[row*HID + h*DK + tx*4 + j] = acc[i][j] * inv;
    }
}

// ---------------- launch -----------------------------------------------------
extern "C" void kernel_launch(void* const* d_in, const int* in_sizes, int n_in,
                              void* d_out, int out_size)
{
    const float* q    = (const float*)d_in[0];
    const float* k    = (const float*)d_in[1];
    const float* v    = (const float*)d_in[2];
    const int*   mask = (const int*)  d_in[3];
    const float* Wq   = (const float*)d_in[4];
    const float* bq   = (const float*)d_in[5];
    const float* Wk   = (const float*)d_in[6];
    const float* bk   = (const float*)d_in[7];
    const float* Wv   = (const float*)d_in[8];
    const float* bv   = (const float*)d_in[9];
    const float* Wo   = (const float*)d_in[10];
    const float* bo   = (const float*)d_in[11];
    float* out = (float*)d_out;

    float *Qh, *Kh, *Vh, *X; unsigned* mb;
    __nv_bfloat16 *Whi, *Wlo, *Ahi, *Alo;
    cudaGetSymbolAddress((void**)&Qh,  g_Qh);
    cudaGetSymbolAddress((void**)&Kh,  g_Kh);
    cudaGetSymbolAddress((void**)&Vh,  g_Vh);
    cudaGetSymbolAddress((void**)&X,   g_X);
    cudaGetSymbolAddress((void**)&Whi, g_Whi);
    cudaGetSymbolAddress((void**)&Wlo, g_Wlo);
    cudaGetSymbolAddress((void**)&Ahi, g_Ahi);
    cudaGetSymbolAddress((void**)&Alo, g_Alo);
    cudaGetSymbolAddress((void**)&mb,  g_mb);

    cudaFuncSetAttribute(gemm_mma_kernel<0>,
                         cudaFuncAttributeMaxDynamicSharedMemorySize, GEMM_SMEM);
    cudaFuncSetAttribute(gemm_mma_kernel<1>,
                         cudaFuncAttributeMaxDynamicSharedMemorySize, GEMM_SMEM);
    cudaFuncSetAttribute(flash_attn_kernel,
                         cudaFuncAttributeMaxDynamicSharedMemorySize, ATT_SMEM);

    // 1) mask bitpack
    pack_mask_kernel<<<(BB*SS*MW + 255)/256, 256>>>(mask, mb);

    // 2) weights: transpose + split (K-major [n][k] hi/lo planes)
    dim3 tg(HID/32, HID/32);
    transpose_split_kernel<<<tg, 256>>>(Wq, Whi + 0L*HID*HID, Wlo + 0L*HID*HID);
    transpose_split_kernel<<<tg, 256>>>(Wk, Whi + 1L*HID*HID, Wlo + 1L*HID*HID);
    transpose_split_kernel<<<tg, 256>>>(Wv, Whi + 2L*HID*HID, Wlo + 2L*HID*HID);
    transpose_split_kernel<<<tg, 256>>>(Wo, Whi + 3L*HID*HID, Wlo + 3L*HID*HID);

    const int n4 = MM*HID/4;
    dim3 gg(HID/128, MM/128);

    // 3) projections on tensor cores (bf16-split, head-split outputs)
    convert_split_kernel<<<(n4 + 255)/256, 256>>>(q, Ahi, Alo, n4);
    gemm_mma_kernel<1><<<gg, 256, GEMM_SMEM>>>(Ahi, Alo,
        Whi + 0L*HID*HID, Wlo + 0L*HID*HID, bq, Qh);
    convert_split_kernel<<<(n4 + 255)/256, 256>>>(k, Ahi, Alo, n4);
    gemm_mma_kernel<1><<<gg, 256, GEMM_SMEM>>>(Ahi, Alo,
        Whi + 1L*HID*HID, Wlo + 1L*HID*HID, bk, Kh);
    convert_split_kernel<<<(n4 + 255)/256, 256>>>(v, Ahi, Alo, n4);
    gemm_mma_kernel<1><<<gg, 256, GEMM_SMEM>>>(Ahi, Alo,
        Whi + 2L*HID*HID, Wlo + 2L*HID*HID, bv, Vh);

    // 4) flash attention
    flash_attn_kernel<<<dim3(SS/64, BB*NH), 256, ATT_SMEM>>>(Qh, Kh, Vh, mb, X);

    // 5) output projection
    convert_split_kernel<<<(n4 + 255)/256, 256>>>(X, Ahi, Alo, n4);
    gemm_mma_kernel<0><<<gg, 256, GEMM_SMEM>>>(Ahi, Alo,
        Whi + 3L*HID*HID, Wlo + 3L*HID*HID, bo, out);
}

// round 4
// speedup vs baseline: 5.1226x; 3.3958x over previous
#include <cuda_runtime.h>
#include <cuda_fp16.h>
#include <math.h>
#include <stdint.h>

#define BB   2
#define SS   2048
#define HID  1024
#define NH   16
#define DK   64
#define MM   (BB*SS)
#define MW   (SS/32)

// ---------------- scratch (device globals) -----------------------------------
__device__ __half   g_Qh[BB*NH*SS*DK];   // [b,h,s,d] fp16
__device__ __half   g_Kh[BB*NH*SS*DK];
__device__ __half   g_Vh[BB*NH*SS*DK];
__device__ __half   g_Xh[MM*HID];        // attention out fp16 [b*s][h*d]
__device__ __half   g_Wh[4*HID*HID];     // transposed weights fp16 [n][k]
__device__ __half   g_Aq[MM*HID];        // fp16 activations
__device__ __half   g_Ak[MM*HID];
__device__ __half   g_Av[MM*HID];
__device__ unsigned g_mb[BB*SS*MW];

// ---------------- helpers ----------------------------------------------------
__device__ __forceinline__ uint32_t smem_u32(const void* p) {
    uint32_t a;
    asm("{ .reg .u64 t; cvta.to.shared.u64 t, %1; cvt.u32.u64 %0, t; }"
        : "=r"(a) : "l"(p));
    return a;
}
__device__ __forceinline__ uint32_t lds32(uint32_t a) {
    uint32_t v; asm volatile("ld.shared.b32 %0, [%1];" : "=r"(v) : "r"(a)); return v;
}
__device__ __forceinline__ uint32_t packh2(float a, float b) {
    __half2 h = __floats2half2_rn(a, b);
    return *reinterpret_cast<uint32_t*>(&h);
}
#define CPA(dst, src) \
    asm volatile("cp.async.ca.shared.global [%0], [%1], 16;" :: "r"(dst), "l"(src))
#define MMA_F16(c, a, b0, b1) \
    asm volatile("mma.sync.aligned.m16n8k16.row.col.f32.f16.f16.f32 " \
                 "{%0,%1,%2,%3},{%4,%5,%6,%7},{%8,%9},{%0,%1,%2,%3};" \
                 : "+f"((c)[0]), "+f"((c)[1]), "+f"((c)[2]), "+f"((c)[3]) \
                 : "r"((a)[0]), "r"((a)[1]), "r"((a)[2]), "r"((a)[3]), \
                   "r"(b0), "r"(b1))
#define LDSM_X2(r0, r1, addr) \
    asm volatile("ldmatrix.sync.aligned.m8n8.x2.shared.b16 {%0,%1}, [%2];" \
                 : "=r"(r0), "=r"(r1) : "r"(addr))
#define LDSM_X2T(r0, r1, addr) \
    asm volatile("ldmatrix.sync.aligned.m8n8.x2.trans.shared.b16 {%0,%1}, [%2];" \
                 : "=r"(r0), "=r"(r1) : "r"(addr))
#define LDSM_X4(r0, r1, r2, r3, addr) \
    asm volatile("ldmatrix.sync.aligned.m8n8.x4.shared.b16 {%0,%1,%2,%3}, [%4];" \
                 : "=r"(r0), "=r"(r1), "=r"(r2), "=r"(r3) : "r"(addr))

// ---------------- mask bit-pack ---------------------------------------------
__global__ __launch_bounds__(256)
void pack_mask_kernel(const int* __restrict__ mask, unsigned* __restrict__ out)
{
    int idx = blockIdx.x * blockDim.x + threadIdx.x;
    if (idx >= BB*SS*MW) return;
    int w = idx % MW;
    int q = (idx / MW) % SS;
    int b = idx / (SS*MW);
    const int* row = mask + ((long)b*SS + q)*SS + (long)w*32;
    unsigned bits = 0;
#pragma unroll
    for (int i = 0; i < 32; i++)
        bits |= (row[i] != 0) ? (1u << i) : 0u;
    out[idx] = bits;
}

// ---------------- weight transpose -> fp16 -----------------------------------
__global__ __launch_bounds__(256)
void transpose_half_kernel(const float* __restrict__ W, __half* __restrict__ T)
{
    __shared__ float tile[32][33];
    const int tx = threadIdx.x & 31, ty = threadIdx.x >> 5;
    const int nb = blockIdx.x * 32, kb = blockIdx.y * 32;
#pragma unroll
    for (int i = 0; i < 32; i += 8)
        tile[ty + i][tx] = W[(long)(kb + ty + i)*HID + nb + tx];
    __syncthreads();
#pragma unroll
    for (int i = 0; i < 32; i += 8)
        T[(long)(nb + ty + i)*HID + kb + tx] = __float2half_rn(tile[tx][ty + i]);
}

// ---------------- fp32 -> fp16 convert ---------------------------------------
__global__ __launch_bounds__(256)
void conv_half_kernel(const float* __restrict__ x, __half* __restrict__ o, int n4)
{
    int i = blockIdx.x * blockDim.x + threadIdx.x;
    if (i >= n4) return;
    float4 v = reinterpret_cast<const float4*>(x)[i];
    __half2* oo = reinterpret_cast<__half2*>(o);
    oo[2*i + 0] = __floats2half2_rn(v.x, v.y);
    oo[2*i + 1] = __floats2half2_rn(v.z, v.w);
}

// ---------------- fp16 single-pass mma GEMM + bias ---------------------------
// C[M,N] = A[M,K] @ W[K,N] + bias; B as [n][k].  CTA 128x128, 8 warps (4m x 2n),
// warp 32x64, k-chunk 32, cp.async double buffer.
#define LDKh 40
#define PSh (128*LDKh*2)     // 10240 B per operand plane
#define BSh (2*PSh)          // 20480 per buffer
#define GEMM_SMEM (2*BSh)    // 40960
#define NCHUNK (HID/32)

template<int MODE>   // 0: fp32 [M][N] out; 1: fp16 head-split [b,h,s,d]
__global__ __launch_bounds__(256, 1)
void gemm_fp16_kernel(const __half* __restrict__ A, const __half* __restrict__ B,
                      const float* __restrict__ bias, void* __restrict__ Cout)
{
    extern __shared__ char smem[];
    const uint32_t sb = smem_u32(smem);
    const int t = threadIdx.x, lane = t & 31;
    const int w = t >> 5;
    const int warp_m = w & 3, warp_n = w >> 2;
    const int g = lane >> 2, tq = lane & 3;
    const int m0 = blockIdx.y * 128, n0 = blockIdx.x * 128;

    float acc[2][8][4];
#pragma unroll
    for (int mf = 0; mf < 2; mf++)
#pragma unroll
        for (int nf = 0; nf < 8; nf++)
#pragma unroll
            for (int r = 0; r < 4; r++) acc[mf][nf][r] = 0.f;

    auto issue = [&](int ck, int buf) {
#pragma unroll
        for (int i = 0; i < 2; i++) {
            const int s = t + i*256;            // 0..511
            const int row = s >> 2, seg = s & 3;
            const uint32_t d = sb + buf*BSh + row*(LDKh*2) + seg*16;
            const long ao = (long)(m0 + row)*HID + ck*32 + seg*8;
            const long bo = (long)(n0 + row)*HID + ck*32 + seg*8;
            CPA(d,       A + ao);
            CPA(d + PSh, B + bo);
        }
        asm volatile("cp.async.commit_group;" ::: "memory");
    };

    issue(0, 0);
    issue(1, 1);

    for (int ck = 0; ck < NCHUNK; ck++) {
        if (ck + 1 < NCHUNK) asm volatile("cp.async.wait_group 1;" ::: "memory");
        else                 asm volatile("cp.async.wait_group 0;" ::: "memory");
        __syncthreads();
        const uint32_t uA = sb + (ck & 1)*BSh;
        const uint32_t uB = uA + PSh;
#pragma unroll
        for (int ks = 0; ks < 2; ks++) {
            const uint32_t acol = ks*32 + tq*4;
            uint32_t a[2][4];
#pragma unroll
            for (int mf = 0; mf < 2; mf++) {
                const uint32_t r = uA + (warp_m*32 + mf*16 + g)*(LDKh*2) + acol;
                a[mf][0] = lds32(r);
                a[mf][1] = lds32(r + 8*(LDKh*2));
                a[mf][2] = lds32(r + 16);
                a[mf][3] = lds32(r + 8*(LDKh*2) + 16);
            }
#pragma unroll
            for (int nf = 0; nf < 8; nf++) {
                const uint32_t rb = uB + (warp_n*64 + nf*8 + g)*(LDKh*2) + acol;
                const uint32_t b0 = lds32(rb), b1 = lds32(rb + 16);
#pragma unroll
                for (int mf = 0; mf < 2; mf++)
                    MMA_F16(acc[mf][nf], a[mf], b0, b1);
            }
        }
        __syncthreads();
        if (ck + 2 < NCHUNK) issue(ck + 2, ck & 1);
    }

#pragma unroll
    for (int nf = 0; nf < 8; nf++) {
        const int cb = n0 + warp_n*64 + nf*8 + 2*tq;
        const float bx = bias[cb], by = bias[cb + 1];
#pragma unroll
        for (int mf = 0; mf < 2; mf++) {
#pragma unroll
            for (int half = 0; half < 2; half++) {
                const int m = m0 + warp_m*32 + mf*16 + g + half*8;
                const float vx = acc[mf][nf][half*2 + 0] + bx;
                const float vy = acc[mf][nf][half*2 + 1] + by;
                if (MODE == 0) {
                    float2 v; v.x = vx; v.y = vy;
                    *reinterpret_cast<float2*>((float*)Cout + (long)m*HID + cb) = v;
                } else {
                    const int b = m >> 11, s = m & 2047;
                    const int h = cb >> 6, d = cb & 63;
                    *reinterpret_cast<uint32_t*>(
                        (__half*)Cout + ((long)((b*NH + h)*SS + s))*DK + d) = packh2(vx, vy);
                }
            }
        }
    }
}

// ---------------- flash attention on mma.sync fp16 ---------------------------
// CTA: 128 q-rows for one (b,h); 8 warps x m16. K-tile 128, double-buffered.
#define ASTRIDE 72                    // halves per smem row (64 data + 8 pad)
#define TILEB (128*ASTRIDE*2)         // 18432 B
#define ATT_SMEM (5*TILEB)            // Q + 2*K + 2*V = 92160

__global__ __launch_bounds__(256, 1)
void attn_mma_kernel(const __half* __restrict__ Qh, const __half* __restrict__ Kh,
                     const __half* __restrict__ Vh, const unsigned* __restrict__ mb,
                     __half* __restrict__ Xh)
{
    extern __shared__ char smem[];
    const uint32_t sb = smem_u32(smem);
    const int t = threadIdx.x, lane = t & 31;
    const int w = t >> 5;
    const int g = lane >> 2, tq = lane & 3;
    const int qt = blockIdx.x, bh = blockIdx.y;
    const int b = bh >> 4, h = bh & 15;
    const int q0 = qt * 128;

    const uint32_t Qs = sb;
    const uint32_t Ksm[2] = { sb + 1*TILEB, sb + 2*TILEB };
    const uint32_t Vsm[2] = { sb + 3*TILEB, sb + 4*TILEB };

    auto issueKV = [&](int kt, int buf) {
#pragma unroll
        for (int i = 0; i < 4; i++) {
            const int s = t + i*256;             // 0..1023
            const int row = s >> 3, seg = s & 7;
            const uint32_t off = row*(ASTRIDE*2) + seg*16;
            const long src = ((long)bh*SS + kt*128 + row)*DK + seg*8;
            CPA(Ksm[buf] + off, Kh + src);
            CPA(Vsm[buf] + off, Vh + src);
        }
        asm volatile("cp.async.commit_group;" ::: "memory");
    };

    // group 0: Q + K0/V0 ; group 1: K1/V1
#pragma unroll
    for (int i = 0; i < 4; i++) {
        const int s = t + i*256;
        const int row = s >> 3, seg = s & 7;
        CPA(Qs + row*(ASTRIDE*2) + seg*16,
            Qh + ((long)bh*SS + q0 + row)*DK + seg*8);
    }
    {
#pragma unroll
        for (int i = 0; i < 4; i++) {
            const int s = t + i*256;
            const int row = s >> 3, seg = s & 7;
            const uint32_t off = row*(ASTRIDE*2) + seg*16;
            const long src = ((long)bh*SS + 0*128 + row)*DK + seg*8;
            CPA(Ksm[0] + off, Kh + src);
            CPA(Vsm[0] + off, Vh + src);
        }
        asm volatile("cp.async.commit_group;" ::: "memory");
    }
    issueKV(1, 1);

    float m_i[2] = {-1e30f, -1e30f}, l_i[2] = {0.f, 0.f};
    float O[8][4];
#pragma unroll
    for (int nf = 0; nf < 8; nf++)
#pragma unroll
        for (int r = 0; r < 4; r++) O[nf][r] = 0.f;

    uint32_t qf[4][4];
    const long mrow0 = ((long)b*SS + q0 + w*16 + g)*MW;
    const long mrow1 = mrow0 + 8L*MW;

    for (int kt = 0; kt < 16; kt++) {
        if (kt + 1 < 16) asm volatile("cp.async.wait_group 1;" ::: "memory");
        else             asm volatile("cp.async.wait_group 0;" ::: "memory");
        __syncthreads();

        if (kt == 0) {
#pragma unroll
            for (int ks = 0; ks < 4; ks++) {
                const uint32_t addr = Qs + (w*16 + (lane & 15))*(ASTRIDE*2)
                                    + (ks*16 + (lane >> 4)*8)*2;
                LDSM_X4(qf[ks][0], qf[ks][1], qf[ks][2], qf[ks][3], addr);
            }
        }
        const uint32_t uK = Ksm[kt & 1], uV = Vsm[kt & 1];

        // ---- S = Q K^T
        float S[16][4];
#pragma unroll
        for (int nf = 0; nf < 16; nf++) {
#pragma unroll
            for (int r = 0; r < 4; r++) S[nf][r] = 0.f;
#pragma unroll
            for (int ks = 0; ks < 4; ks++) {
                uint32_t b0, b1;
                const uint32_t addr = uK + (nf*8 + (lane & 7))*(ASTRIDE*2)
                                    + (ks*16 + ((lane >> 3) & 1)*8)*2;
                LDSM_X2(b0, b1, addr);
                MMA_F16(S[nf], qf[ks], b0, b1);
            }
        }

        // ---- mask words
        unsigned mw0[4], mw1[4];
#pragma unroll
        for (int j = 0; j < 4; j++) {
            mw0[j] = mb[mrow0 + kt*4 + j];
            mw1[j] = mb[mrow1 + kt*4 + j];
        }

        // ---- row max
        float mx0 = -1e30f, mx1 = -1e30f;
#pragma unroll
        for (int nf = 0; nf < 16; nf++) {
            const int sh = ((nf & 3) << 3) + (tq << 1);
            const unsigned bt0 = (mw0[nf >> 2] >> sh) & 3u;
            const unsigned bt1 = (mw1[nf >> 2] >> sh) & 3u;
            if (bt0 & 1) mx0 = fmaxf(mx0, S[nf][0]*0.125f);
            if (bt0 & 2) mx0 = fmaxf(mx0, S[nf][1]*0.125f);
            if (bt1 & 1) mx1 = fmaxf(mx1, S[nf][2]*0.125f);
            if (bt1 & 2) mx1 = fmaxf(mx1, S[nf][3]*0.125f);
        }
#pragma unroll
        for (int off = 1; off < 4; off <<= 1) {
            mx0 = fmaxf(mx0, __shfl_xor_sync(0xffffffffu, mx0, off));
            mx1 = fmaxf(mx1, __shfl_xor_sync(0xffffffffu, mx1, off));
        }
        const float mn0 = fmaxf(m_i[0], mx0), mn1 = fmaxf(m_i[1], mx1);
        const float al0 = __expf(m_i[0] - mn0), al1 = __expf(m_i[1] - mn1);
        m_i[0] = mn0; m_i[1] = mn1;

        // ---- P = exp(S - m), pack to fp16 A-frags, row sums
        float rs0 = 0.f, rs1 = 0.f;
        uint32_t pf[8][4];
#pragma unroll
        for (int nf = 0; nf < 16; nf++) {
            const int sh = ((nf & 3) << 3) + (tq << 1);
            const unsigned bt0 = (mw0[nf >> 2] >> sh) & 3u;
            const unsigned bt1 = (mw1[nf >> 2] >> sh) & 3u;
            const float p00 = (bt0 & 1) ? __expf(S[nf][0]*0.125f - mn0) : 0.f;
            const float p01 = (bt0 & 2) ? __expf(S[nf][1]*0.125f - mn0) : 0.f;
            const float p10 = (bt1 & 1) ? __expf(S[nf][2]*0.125f - mn1) : 0.f;
            const float p11 = (bt1 & 2) ? __expf(S[nf][3]*0.125f - mn1) : 0.f;
            rs0 += p00 + p01; rs1 += p10 + p11;
            const int ks = nf >> 1, half = (nf & 1) << 1;
            pf[ks][half + 0] = packh2(p00, p01);
            pf[ks][half + 1] = packh2(p10, p11);
        }
#pragma unroll
        for (int off = 1; off < 4; off <<= 1) {
            rs0 += __shfl_xor_sync(0xffffffffu, rs0, off);
            rs1 += __shfl_xor_sync(0xffffffffu, rs1, off);
        }
        l_i[0] = l_i[0]*al0 + rs0;
        l_i[1] = l_i[1]*al1 + rs1;
#pragma unroll
        for (int nf = 0; nf < 8; nf++) {
            O[nf][0] *= al0; O[nf][1] *= al0;
            O[nf][2] *= al1; O[nf][3] *= al1;
        }

        // ---- O += P V  (V via ldmatrix.trans, B = V^T frags)
#pragma unroll
        for (int nf = 0; nf < 8; nf++) {
#pragma unroll
            for (int ks = 0; ks < 8; ks++) {
                uint32_t v0, v1;
                const uint32_t addr = uV + (ks*16 + (lane & 15))*(ASTRIDE*2) + nf*16;
                LDSM_X2T(v0, v1, addr);
                MMA_F16(O[nf], pf[ks], v0, v1);
            }
        }
        __syncthreads();
        if (kt + 2 < 16) issueKV(kt + 2, kt & 1);
    }

    // ---- epilogue
    const float in0 = (l_i[0] > 0.f) ? (1.f / l_i[0]) : 0.f;
    const float in1 = (l_i[1] > 0.f) ? (1.f / l_i[1]) : 0.f;
    const long r0 = (long)(b*SS + q0 + w*16 + g);
    const long r1 = r0 + 8;
#pragma unroll
    for (int nf = 0; nf < 8; nf++) {
        const int d = h*64 + nf*8 + tq*2;
        *reinterpret_cast<uint32_t*>(Xh + r0*HID + d) = packh2(O[nf][0]*in0, O[nf][1]*in0);
        *reinterpret_cast<uint32_t*>(Xh + r1*HID + d) = packh2(O[nf][2]*in1, O[nf][3]*in1);
    }
}

// ---------------- launch -----------------------------------------------------
extern "C" void kernel_launch(void* const* d_in, const int* in_sizes, int n_in,
                              void* d_out, int out_size)
{
    const float* q    = (const float*)d_in[0];
    const float* k    = (const float*)d_in[1];
    const float* v    = (const float*)d_in[2];
    const int*   mask = (const int*)  d_in[3];
    const float* Wq   = (const float*)d_in[4];
    const float* bq   = (const float*)d_in[5];
    const float* Wk   = (const float*)d_in[6];
    const float* bk   = (const float*)d_in[7];
    const float* Wv   = (const float*)d_in[8];
    const float* bv   = (const float*)d_in[9];
    const float* Wo   = (const float*)d_in[10];
    const float* bo   = (const float*)d_in[11];
    float* out = (float*)d_out;

    __half *Qh, *Kh, *Vh, *Xh, *Wh, *Aq, *Ak, *Av; unsigned* mbp;
    cudaGetSymbolAddress((void**)&Qh, g_Qh);
    cudaGetSymbolAddress((void**)&Kh, g_Kh);
    cudaGetSymbolAddress((void**)&Vh, g_Vh);
    cudaGetSymbolAddress((void**)&Xh, g_Xh);
    cudaGetSymbolAddress((void**)&Wh, g_Wh);
    cudaGetSymbolAddress((void**)&Aq, g_Aq);
    cudaGetSymbolAddress((void**)&Ak, g_Ak);
    cudaGetSymbolAddress((void**)&Av, g_Av);
    cudaGetSymbolAddress((void**)&mbp, g_mb);

    cudaFuncSetAttribute(gemm_fp16_kernel<0>,
                         cudaFuncAttributeMaxDynamicSharedMemorySize, GEMM_SMEM);
    cudaFuncSetAttribute(gemm_fp16_kernel<1>,
                         cudaFuncAttributeMaxDynamicSharedMemorySize, GEMM_SMEM);
    cudaFuncSetAttribute(attn_mma_kernel,
                         cudaFuncAttributeMaxDynamicSharedMemorySize, ATT_SMEM);

    pack_mask_kernel<<<(BB*SS*MW + 255)/256, 256>>>(mask, mbp);

    dim3 tg(HID/32, HID/32);
    transpose_half_kernel<<<tg, 256>>>(Wq, Wh + 0L*HID*HID);
    transpose_half_kernel<<<tg, 256>>>(Wk, Wh + 1L*HID*HID);
    transpose_half_kernel<<<tg, 256>>>(Wv, Wh + 2L*HID*HID);
    transpose_half_kernel<<<tg, 256>>>(Wo, Wh + 3L*HID*HID);

    const int n4 = MM*HID/4;
    conv_half_kernel<<<(n4 + 255)/256, 256>>>(q, Aq, n4);
    conv_half_kernel<<<(n4 + 255)/256, 256>>>(k, Ak, n4);
    conv_half_kernel<<<(n4 + 255)/256, 256>>>(v, Av, n4);

    dim3 gg(HID/128, MM/128);
    gemm_fp16_kernel<1><<<gg, 256, GEMM_SMEM>>>(Aq, Wh + 0L*HID*HID, bq, Qh);
    gemm_fp16_kernel<1><<<gg, 256, GEMM_SMEM>>>(Ak, Wh + 1L*HID*HID, bk, Kh);
    gemm_fp16_kernel<1><<<gg, 256, GEMM_SMEM>>>(Av, Wh + 2L*HID*HID, bv, Vh);

    attn_mma_kernel<<<dim3(SS/128, BB*NH), 256, ATT_SMEM>>>(Qh, Kh, Vh, mbp, Xh);

    gemm_fp16_kernel<0><<<gg, 256, GEMM_SMEM>>>(Xh, Wh + 3L*HID*HID, bo, out);
}

// round 6
// speedup vs baseline: 6.4077x; 1.2509x over previous
#include <cuda_runtime.h>
#include <cuda_fp16.h>
#include <math.h>
#include <stdint.h>

#define BB   2
#define SS   2048
#define HID  1024
#define NH   16
#define DK   64
#define MM   (BB*SS)
#define MW   (SS/32)

// ---------------- scratch (device globals) -----------------------------------
__device__ __half   g_Qh[BB*NH*SS*DK];   // [b,h,s,d] fp16
__device__ __half   g_Kh[BB*NH*SS*DK];
__device__ __half   g_Vh[BB*NH*SS*DK];
__device__ __half   g_Xh[MM*HID];        // attention out fp16 [b*s][h*d]
__device__ __half   g_Wh[4*HID*HID];     // transposed weights fp16 [n][k]
__device__ unsigned g_mb[BB*SS*MW];

// ---------------- helpers ----------------------------------------------------
__device__ __forceinline__ uint32_t smem_u32(const void* p) {
    uint32_t a;
    asm("{ .reg .u64 t; cvta.to.shared.u64 t, %1; cvt.u32.u64 %0, t; }"
        : "=r"(a) : "l"(p));
    return a;
}
__device__ __forceinline__ uint32_t lds32(uint32_t a) {
    uint32_t v; asm volatile("ld.shared.b32 %0, [%1];" : "=r"(v) : "r"(a)); return v;
}
__device__ __forceinline__ float2 ldsf2(uint32_t a) {
    float2 v;
    asm volatile("ld.shared.v2.f32 {%0,%1}, [%2];" : "=f"(v.x), "=f"(v.y) : "r"(a));
    return v;
}
__device__ __forceinline__ uint32_t packh2(float a, float b) {
    __half2 h = __floats2half2_rn(a, b);
    return *reinterpret_cast<uint32_t*>(&h);
}
__device__ __forceinline__ uint32_t h2ex2(uint32_t x) {
    uint32_t r; asm("ex2.approx.f16x2 %0, %1;" : "=r"(r) : "r"(x)); return r;
}
__device__ __forceinline__ float fex2(float x) {
    float r; asm("ex2.approx.f32 %0, %1;" : "=f"(r) : "f"(x)); return r;
}
#define CPA(dst, src) \
    asm volatile("cp.async.ca.shared.global [%0], [%1], 16;" :: "r"(dst), "l"(src))
#define MMA_F16(c, a, b0, b1) \
    asm volatile("mma.sync.aligned.m16n8k16.row.col.f32.f16.f16.f32 " \
                 "{%0,%1,%2,%3},{%4,%5,%6,%7},{%8,%9},{%0,%1,%2,%3};" \
                 : "+f"((c)[0]), "+f"((c)[1]), "+f"((c)[2]), "+f"((c)[3]) \
                 : "r"((a)[0]), "r"((a)[1]), "r"((a)[2]), "r"((a)[3]), \
                   "r"(b0), "r"(b1))
#define LDSM_X2(r0, r1, addr) \
    asm volatile("ldmatrix.sync.aligned.m8n8.x2.shared.b16 {%0,%1}, [%2];" \
                 : "=r"(r0), "=r"(r1) : "r"(addr))
#define LDSM_X2T(r0, r1, addr) \
    asm volatile("ldmatrix.sync.aligned.m8n8.x2.trans.shared.b16 {%0,%1}, [%2];" \
                 : "=r"(r0), "=r"(r1) : "r"(addr))
#define LDSM_X4(r0, r1, r2, r3, addr) \
    asm volatile("ldmatrix.sync.aligned.m8n8.x4.shared.b16 {%0,%1,%2,%3}, [%4];" \
                 : "=r"(r0), "=r"(r1), "=r"(r2), "=r"(r3) : "r"(addr))

// ---------------- mask bit-pack ---------------------------------------------
__global__ __launch_bounds__(256)
void pack_mask_kernel(const int* __restrict__ mask, unsigned* __restrict__ out)
{
    int idx = blockIdx.x * blockDim.x + threadIdx.x;
    if (idx >= BB*SS*MW) return;
    int w = idx % MW;
    int q = (idx / MW) % SS;
    int b = idx / (SS*MW);
    const int* row = mask + ((long)b*SS + q)*SS + (long)w*32;
    unsigned bits = 0;
#pragma unroll
    for (int i = 0; i < 32; i++)
        bits |= (row[i] != 0) ? (1u << i) : 0u;
    out[idx] = bits;
}

// ---------------- batched weight transpose -> fp16 ---------------------------
__global__ __launch_bounds__(256)
void transpose4_kernel(const float* __restrict__ W0, const float* __restrict__ W1,
                       const float* __restrict__ W2, const float* __restrict__ W3,
                       __half* __restrict__ T)
{
    __shared__ float tile[32][33];
    const int z = blockIdx.z;
    const float* W = (z == 0) ? W0 : (z == 1) ? W1 : (z == 2) ? W2 : W3;
    __half* out = T + (long)z*HID*HID;
    const int tx = threadIdx.x & 31, ty = threadIdx.x >> 5;
    const int nb = blockIdx.x * 32, kb = blockIdx.y * 32;
#pragma unroll
    for (int i = 0; i < 32; i += 8)
        tile[ty + i][tx] = W[(long)(kb + ty + i)*HID + nb + tx];
    __syncthreads();
#pragma unroll
    for (int i = 0; i < 32; i += 8)
        out[(long)(nb + ty + i)*HID + kb + tx] = __float2half_rn(tile[tx][ty + i]);
}

// ---------------- mma GEMM + bias --------------------------------------------
// C[M,N] = A[M,K] @ W[K,N] + bias; B fp16 [n][k].
// ADT 0: A fp32 (converted at frag-load time). ADT 1: A fp16.
// MODE 0: fp32 [M][N] out. MODE 1: fp16 head-split [b,h,s,d].
// CTA 128x128, 8 warps (4m x 2n), warp 32x64, k-chunk 32, double buffer.
#define NCHUNK (HID/32)

template<int ADT, int MODE>
__global__ __launch_bounds__(256, 2)
void gemm_mma_kernel(const void* __restrict__ Ain, const __half* __restrict__ B,
                     const float* __restrict__ bias, void* __restrict__ Cout)
{
    constexpr int AST  = (ADT == 0) ? 160 : 80;     // A smem row stride bytes
    constexpr int ABUF = 128 * AST;                 // A buffer bytes
    extern __shared__ char smem[];
    const uint32_t sb = smem_u32(smem);
    const int t = threadIdx.x, lane = t & 31;
    const int w = t >> 5;
    const int warp_m = w & 3, warp_n = w >> 2;
    const int g = lane >> 2, tq = lane & 3;
    const int m0 = blockIdx.y * 128, n0 = blockIdx.x * 128;

    const float*  A32 = (const float*)Ain;
    const __half* A16 = (const __half*)Ain;

    float acc[2][8][4];
#pragma unroll
    for (int mf = 0; mf < 2; mf++)
#pragma unroll
        for (int nf = 0; nf < 8; nf++)
#pragma unroll
            for (int r = 0; r < 4; r++) acc[mf][nf][r] = 0.f;

    auto issue = [&](int ck, int buf) {
        if (ADT == 0) {
#pragma unroll
            for (int i = 0; i < 4; i++) {
                const int s = t + i*256;            // 0..1023
                const int row = s >> 3, seg = s & 7;
                CPA(sb + buf*ABUF + row*AST + seg*16,
                    A32 + (long)(m0 + row)*HID + ck*32 + seg*4);
            }
        } else {
#pragma unroll
            for (int i = 0; i < 2; i++) {
                const int s = t + i*256;            // 0..511
                const int row = s >> 2, seg = s & 3;
                CPA(sb + buf*ABUF + row*AST + seg*16,
                    A16 + (long)(m0 + row)*HID + ck*32 + seg*8);
            }
        }
#pragma unroll
        for (int i = 0; i < 2; i++) {
            const int s = t + i*256;
            const int row = s >> 2, seg = s & 3;
            CPA(sb + 2*ABUF + buf*10240 + row*80 + seg*16,
                B + (long)(n0 + row)*HID + ck*32 + seg*8);
        }
        asm volatile("cp.async.commit_group;" ::: "memory");
    };

    issue(0, 0);
    issue(1, 1);

    for (int ck = 0; ck < NCHUNK; ck++) {
        if (ck + 1 < NCHUNK) asm volatile("cp.async.wait_group 1;" ::: "memory");
        else                 asm volatile("cp.async.wait_group 0;" ::: "memory");
        __syncthreads();
        const uint32_t uA = sb + (ck & 1)*ABUF;
        const uint32_t uB = sb + 2*ABUF + (ck & 1)*10240;
#pragma unroll
        for (int ks = 0; ks < 2; ks++) {
            uint32_t a[2][4];
#pragma unroll
            for (int mf = 0; mf < 2; mf++) {
                const int rrow = warp_m*32 + mf*16 + g;
                if (ADT == 0) {
                    const uint32_t r = uA + rrow*AST + ks*64 + tq*8;
                    float2 v0 = ldsf2(r);
                    float2 v1 = ldsf2(r + 8*AST);
                    float2 v2 = ldsf2(r + 32);
                    float2 v3 = ldsf2(r + 8*AST + 32);
                    a[mf][0] = packh2(v0.x, v0.y);
                    a[mf][1] = packh2(v1.x, v1.y);
                    a[mf][2] = packh2(v2.x, v2.y);
                    a[mf][3] = packh2(v3.x, v3.y);
                } else {
                    const uint32_t r = uA + rrow*AST + ks*32 + tq*4;
                    a[mf][0] = lds32(r);
                    a[mf][1] = lds32(r + 8*AST);
                    a[mf][2] = lds32(r + 16);
                    a[mf][3] = lds32(r + 8*AST + 16);
                }
            }
#pragma unroll
            for (int nf = 0; nf < 8; nf++) {
                const uint32_t rb = uB + (warp_n*64 + nf*8 + g)*80 + ks*32 + tq*4;
                const uint32_t b0 = lds32(rb), b1 = lds32(rb + 16);
#pragma unroll
                for (int mf = 0; mf < 2; mf++)
                    MMA_F16(acc[mf][nf], a[mf], b0, b1);
            }
        }
        __syncthreads();
        if (ck + 2 < NCHUNK) issue(ck + 2, ck & 1);
    }

#pragma unroll
    for (int nf = 0; nf < 8; nf++) {
        const int cb = n0 + warp_n*64 + nf*8 + 2*tq;
        const float bx = bias[cb], by = bias[cb + 1];
#pragma unroll
        for (int mf = 0; mf < 2; mf++) {
#pragma unroll
            for (int half = 0; half < 2; half++) {
                const int m = m0 + warp_m*32 + mf*16 + g + half*8;
                const float vx = acc[mf][nf][half*2 + 0] + bx;
                const float vy = acc[mf][nf][half*2 + 1] + by;
                if (MODE == 0) {
                    float2 v; v.x = vx; v.y = vy;
                    *reinterpret_cast<float2*>((float*)Cout + (long)m*HID + cb) = v;
                } else {
                    const int b = m >> 11, s = m & 2047;
                    const int h = cb >> 6, d = cb & 63;
                    *reinterpret_cast<uint32_t*>(
                        (__half*)Cout + ((long)((b*NH + h)*SS + s))*DK + d) = packh2(vx, vy);
                }
            }
        }
    }
}

#define GEMM_SMEM0 (2*128*160 + 2*10240)   // 61440
#define GEMM_SMEM1 (2*128*80  + 2*10240)   // 40960

// ---------------- flash attention on mma.sync fp16 ---------------------------
// CTA: 128 q-rows, one (b,h); 8 warps x m16. K-tile 64, double-buffered.
// Softmax in log2 domain with ex2.approx.f16x2.
#define ASTRIDE 72                    // halves per smem row (64 data + 8 pad)
#define QTILEB (128*ASTRIDE*2)        // 18432
#define KTILEB (64*ASTRIDE*2)         // 9216
#define ATT_SMEM (QTILEB + 4*KTILEB)  // 55296
#define NKT (SS/64)                   // 32 k-tiles

__global__ __launch_bounds__(256, 2)
void attn_mma_kernel(const __half* __restrict__ Qh, const __half* __restrict__ Kh,
                     const __half* __restrict__ Vh, const unsigned* __restrict__ mb,
                     __half* __restrict__ Xh)
{
    extern __shared__ char smem[];
    const uint32_t sb = smem_u32(smem);
    const int t = threadIdx.x, lane = t & 31;
    const int w = t >> 5;
    const int g = lane >> 2, tq = lane & 3;
    const int qt = blockIdx.x, bh = blockIdx.y;
    const int b = bh >> 4, h = bh & 15;
    const int q0 = qt * 128;

    const uint32_t Qs = sb;
    const uint32_t Ksm[2] = { sb + QTILEB,             sb + QTILEB + KTILEB };
    const uint32_t Vsm[2] = { sb + QTILEB + 2*KTILEB,  sb + QTILEB + 3*KTILEB };

    // K/V tile: 64 rows x 8 segs of 16B = 512 cp.asyncs (2 per thread each)
    auto issueKV = [&](int kt, int buf) {
#pragma unroll
        for (int i = 0; i < 2; i++) {
            const int s = t + i*256;                 // 0..511
            const int row = s >> 3, seg = s & 7;     // row 0..63, seg 0..7
            const uint32_t off = row*(ASTRIDE*2) + seg*16;
            const long src = ((long)bh*SS + kt*64 + row)*DK + seg*8;
            CPA(Ksm[buf] + off, Kh + src);
            CPA(Vsm[buf] + off, Vh + src);
        }
        asm volatile("cp.async.commit_group;" ::: "memory");
    };

    // Q tile: 128 rows x 8 segs = 1024 cp.asyncs (4 per thread)
#pragma unroll
    for (int i = 0; i < 4; i++) {
        const int s = t + i*256;                     // 0..1023
        const int row = s >> 3, seg = s & 7;         // row 0..127, seg 0..7
        CPA(Qs + row*(ASTRIDE*2) + seg*16,
            Qh + ((long)bh*SS + q0 + row)*DK + seg*8);
    }
    issueKV(0, 0);   // group 0: Q + K0/V0
    issueKV(1, 1);   // group 1: K1/V1

    float m_i[2] = {-1e30f, -1e30f}, l_i[2] = {0.f, 0.f};
    float O[8][4];
#pragma unroll
    for (int nf = 0; nf < 8; nf++)
#pragma unroll
        for (int r = 0; r < 4; r++) O[nf][r] = 0.f;

    uint32_t qf[4][4];
    const long mrow0 = ((long)b*SS + q0 + w*16 + g)*MW;
    const long mrow1 = mrow0 + 8L*MW;
    const float c1 = 0.1803368801111f;    // 0.125 * log2(e)

    for (int kt = 0; kt < NKT; kt++) {
        if (kt + 1 < NKT) asm volatile("cp.async.wait_group 1;" ::: "memory");
        else             asm volatile("cp.async.wait_group 0;" ::: "memory");
        __syncthreads();

        if (kt == 0) {
#pragma unroll
            for (int ks = 0; ks < 4; ks++) {
                const uint32_t addr = Qs + (w*16 + (lane & 15))*(ASTRIDE*2)
                                    + (ks*16 + (lane >> 4)*8)*2;
                LDSM_X4(qf[ks][0], qf[ks][1], qf[ks][2], qf[ks][3], addr);
            }
        }
        const uint32_t uK = Ksm[kt & 1], uV = Vsm[kt & 1];

        // ---- S = Q K^T (then scaled into log2 units)
        float S[8][4];
#pragma unroll
        for (int nf = 0; nf < 8; nf++) {
#pragma unroll
            for (int r = 0; r < 4; r++) S[nf][r] = 0.f;
#pragma unroll
            for (int ks = 0; ks < 4; ks++) {
                uint32_t b0, b1;
                const uint32_t addr = uK + (nf*8 + (lane & 7))*(ASTRIDE*2)
                                    + (ks*16 + ((lane >> 3) & 1)*8)*2;
                LDSM_X2(b0, b1, addr);
                MMA_F16(S[nf], qf[ks], b0, b1);
            }
#pragma unroll
            for (int r = 0; r < 4; r++) S[nf][r] *= c1;
        }

        // ---- mask words (2 per 64-col tile per row-half)
        unsigned mw0[2], mw1[2];
#pragma unroll
        for (int j = 0; j < 2; j++) {
            mw0[j] = mb[mrow0 + kt*2 + j];
            mw1[j] = mb[mrow1 + kt*2 + j];
        }

        // ---- row max (log2 units)
        float mx0 = -1e30f, mx1 = -1e30f;
#pragma unroll
        for (int nf = 0; nf < 8; nf++) {
            const int sh = ((nf & 3) << 3) + (tq << 1);
            const unsigned bt0 = (mw0[nf >> 2] >> sh) & 3u;
            const unsigned bt1 = (mw1[nf >> 2] >> sh) & 3u;
            if (bt0 & 1) mx0 = fmaxf(mx0, S[nf][0]);
            if (bt0 & 2) mx0 = fmaxf(mx0, S[nf][1]);
            if (bt1 & 1) mx1 = fmaxf(mx1, S[nf][2]);
            if (bt1 & 2) mx1 = fmaxf(mx1, S[nf][3]);
        }
#pragma unroll
        for (int off = 1; off < 4; off <<= 1) {
            mx0 = fmaxf(mx0, __shfl_xor_sync(0xffffffffu, mx0, off));
            mx1 = fmaxf(mx1, __shfl_xor_sync(0xffffffffu, mx1, off));
        }
        const float mn0 = fmaxf(m_i[0], mx0), mn1 = fmaxf(m_i[1], mx1);
        const float al0 = fex2(m_i[0] - mn0), al1 = fex2(m_i[1] - mn1);
        m_i[0] = mn0; m_i[1] = mn1;

        // ---- P = 2^(S - m) via f16x2 ex2; P frags double as PV A-operands
        float rs0 = 0.f, rs1 = 0.f;
        uint32_t pf[4][4];
#pragma unroll
        for (int nf = 0; nf < 8; nf++) {
            const int sh = ((nf & 3) << 3) + (tq << 1);
            const unsigned bt0 = (mw0[nf >> 2] >> sh) & 3u;
            const unsigned bt1 = (mw1[nf >> 2] >> sh) & 3u;
            const float a00 = (bt0 & 1) ? (S[nf][0] - mn0) : -1e4f;
            const float a01 = (bt0 & 2) ? (S[nf][1] - mn0) : -1e4f;
            const float a10 = (bt1 & 1) ? (S[nf][2] - mn1) : -1e4f;
            const float a11 = (bt1 & 2) ? (S[nf][3] - mn1) : -1e4f;
            const uint32_t p0 = h2ex2(packh2(a00, a01));
            const uint32_t p1 = h2ex2(packh2(a10, a11));
            const int ks = nf >> 1, half = (nf & 1) << 1;
            pf[ks][half + 0] = p0;
            pf[ks][half + 1] = p1;
            const float2 f0 = __half22float2(*reinterpret_cast<const __half2*>(&p0));
            const float2 f1 = __half22float2(*reinterpret_cast<const __half2*>(&p1));
            rs0 += f0.x + f0.y;
            rs1 += f1.x + f1.y;
        }
#pragma unroll
        for (int off = 1; off < 4; off <<= 1) {
            rs0 += __shfl_xor_sync(0xffffffffu, rs0, off);
            rs1 += __shfl_xor_sync(0xffffffffu, rs1, off);
        }
        l_i[0] = l_i[0]*al0 + rs0;
        l_i[1] = l_i[1]*al1 + rs1;
#pragma unroll
        for (int nf = 0; nf < 8; nf++) {
            O[nf][0] *= al0; O[nf][1] *= al0;
            O[nf][2] *= al1; O[nf][3] *= al1;
        }

        // ---- O += P V  (V via ldmatrix.trans)
#pragma unroll
        for (int nf = 0; nf < 8; nf++) {
#pragma unroll
            for (int ks = 0; ks < 4; ks++) {
                uint32_t v0, v1;
                const uint32_t addr = uV + (ks*16 + (lane & 15))*(ASTRIDE*2) + nf*16;
                LDSM_X2T(v0, v1, addr);
                MMA_F16(O[nf], pf[ks], v0, v1);
            }
        }
        __syncthreads();
        if (kt + 2 < NKT) issueKV(kt + 2, kt & 1);
    }

    // ---- epilogue
    const float in0 = (l_i[0] > 0.f) ? (1.f / l_i[0]) : 0.f;
    const float in1 = (l_i[1] > 0.f) ? (1.f / l_i[1]) : 0.f;
    const long r0 = (long)(b*SS + q0 + w*16 + g);
    const long r1 = r0 + 8;
#pragma unroll
    for (int nf = 0; nf < 8; nf++) {
        const int d = h*64 + nf*8 + tq*2;
        *reinterpret_cast<uint32_t*>(Xh + r0*HID + d) = packh2(O[nf][0]*in0, O[nf][1]*in0);
        *reinterpret_cast<uint32_t*>(Xh + r1*HID + d) = packh2(O[nf][2]*in1, O[nf][3]*in1);
    }
}

// ---------------- launch -----------------------------------------------------
extern "C" void kernel_launch(void* const* d_in, const int* in_sizes, int n_in,
                              void* d_out, int out_size)
{
    const float* q    = (const float*)d_in[0];
    const float* k    = (const float*)d_in[1];
    const float* v    = (const float*)d_in[2];
    const int*   mask = (const int*)  d_in[3];
    const float* Wq   = (const float*)d_in[4];
    const float* bq   = (const float*)d_in[5];
    const float* Wk   = (const float*)d_in[6];
    const float* bk   = (const float*)d_in[7];
    const float* Wv   = (const float*)d_in[8];
    const float* bv   = (const float*)d_in[9];
    const float* Wo   = (const float*)d_in[10];
    const float* bo   = (const float*)d_in[11];
    float* out = (float*)d_out;

    __half *Qh, *Kh, *Vh, *Xh, *Wh; unsigned* mbp;
    cudaGetSymbolAddress((void**)&Qh, g_Qh);
    cudaGetSymbolAddress((void**)&Kh, g_Kh);
    cudaGetSymbolAddress((void**)&Vh, g_Vh);
    cudaGetSymbolAddress((void**)&Xh, g_Xh);
    cudaGetSymbolAddress((void**)&Wh, g_Wh);
    cudaGetSymbolAddress((void**)&mbp, g_mb);

    cudaFuncSetAttribute((const void*)gemm_mma_kernel<0,1>,
                         cudaFuncAttributeMaxDynamicSharedMemorySize, GEMM_SMEM0);
    cudaFuncSetAttribute((const void*)gemm_mma_kernel<1,0>,
                         cudaFuncAttributeMaxDynamicSharedMemorySize, GEMM_SMEM1);
    cudaFuncSetAttribute((const void*)attn_mma_kernel,
                         cudaFuncAttributeMaxDynamicSharedMemorySize, ATT_SMEM);

    pack_mask_kernel<<<(BB*SS*MW + 255)/256, 256>>>(mask, mbp);

    transpose4_kernel<<<dim3(HID/32, HID/32, 4), 256>>>(Wq, Wk, Wv, Wo, Wh);

    dim3 gg(HID/128, MM/128);
    gemm_mma_kernel<0,1><<<gg, 256, GEMM_SMEM0>>>(q, Wh + 0L*HID*HID, bq, Qh);
    gemm_mma_kernel<0,1><<<gg, 256, GEMM_SMEM0>>>(k, Wh + 1L*HID*HID, bk, Kh);
    gemm_mma_kernel<0,1><<<gg, 256, GEMM_SMEM0>>>(v, Wh + 2L*HID*HID, bv, Vh);

    attn_mma_kernel<<<dim3(SS/128, BB*NH), 256, ATT_SMEM>>>(Qh, Kh, Vh, mbp, Xh);

    gemm_mma_kernel<1,0><<<gg, 256, GEMM_SMEM1>>>(Xh, Wh + 3L*HID*HID, bo, out);
}

// round 7
// speedup vs baseline: 6.7126x; 1.0476x over previous
#include <cuda_runtime.h>
#include <cuda_fp16.h>
#include <math.h>
#include <stdint.h>

#define BB   2
#define SS   2048
#define HID  1024
#define NH   16
#define DK   64
#define MM   (BB*SS)
#define MW   (SS/32)

// ---------------- scratch (device globals) -----------------------------------
__device__ __half   g_Qh[BB*NH*SS*DK];   // [b,h,s,d] fp16
__device__ __half   g_Kh[BB*NH*SS*DK];
__device__ __half   g_Vh[BB*NH*SS*DK];
__device__ __half   g_Xh[MM*HID];        // attention out fp16 [b*s][h*d]
__device__ __half   g_Wh[4*HID*HID];     // transposed weights fp16 [n][k]
__device__ unsigned g_mb[BB*SS*MW];

// ---------------- helpers ----------------------------------------------------
__device__ __forceinline__ uint32_t smem_u32(const void* p) {
    uint32_t a;
    asm("{ .reg .u64 t; cvta.to.shared.u64 t, %1; cvt.u32.u64 %0, t; }"
        : "=r"(a) : "l"(p));
    return a;
}
__device__ __forceinline__ float2 ldsf2(uint32_t a) {
    float2 v;
    asm volatile("ld.shared.v2.f32 {%0,%1}, [%2];" : "=f"(v.x), "=f"(v.y) : "r"(a));
    return v;
}
__device__ __forceinline__ uint32_t packh2(float a, float b) {
    __half2 h = __floats2half2_rn(a, b);
    return *reinterpret_cast<uint32_t*>(&h);
}
__device__ __forceinline__ uint32_t h2ex2(uint32_t x) {
    uint32_t r; asm("ex2.approx.f16x2 %0, %1;" : "=r"(r) : "r"(x)); return r;
}
__device__ __forceinline__ float fex2(float x) {
    float r; asm("ex2.approx.f32 %0, %1;" : "=f"(r) : "f"(x)); return r;
}
#define CPA(dst, src) \
    asm volatile("cp.async.ca.shared.global [%0], [%1], 16;" :: "r"(dst), "l"(src))
#define CPCOMMIT() asm volatile("cp.async.commit_group;" ::: "memory")
#define MMA_F16(c, a, b0, b1) \
    asm volatile("mma.sync.aligned.m16n8k16.row.col.f32.f16.f16.f32 " \
                 "{%0,%1,%2,%3},{%4,%5,%6,%7},{%8,%9},{%0,%1,%2,%3};" \
                 : "+f"((c)[0]), "+f"((c)[1]), "+f"((c)[2]), "+f"((c)[3]) \
                 : "r"((a)[0]), "r"((a)[1]), "r"((a)[2]), "r"((a)[3]), \
                   "r"(b0), "r"(b1))
#define LDSM_X4(r0, r1, r2, r3, addr) \
    asm volatile("ldmatrix.sync.aligned.m8n8.x4.shared.b16 {%0,%1,%2,%3}, [%4];" \
                 : "=r"(r0), "=r"(r1), "=r"(r2), "=r"(r3) : "r"(addr))
#define LDSM_X4T(r0, r1, r2, r3, addr) \
    asm volatile("ldmatrix.sync.aligned.m8n8.x4.trans.shared.b16 {%0,%1,%2,%3}, [%4];" \
                 : "=r"(r0), "=r"(r1), "=r"(r2), "=r"(r3) : "r"(addr))

// ---------------- mask bit-pack ---------------------------------------------
__global__ __launch_bounds__(256)
void pack_mask_kernel(const int* __restrict__ mask, unsigned* __restrict__ out)
{
    int idx = blockIdx.x * blockDim.x + threadIdx.x;
    if (idx >= BB*SS*MW) return;
    int w = idx % MW;
    int q = (idx / MW) % SS;
    int b = idx / (SS*MW);
    const int* row = mask + ((long)b*SS + q)*SS + (long)w*32;
    unsigned bits = 0;
#pragma unroll
    for (int i = 0; i < 32; i++)
        bits |= (row[i] != 0) ? (1u << i) : 0u;
    out[idx] = bits;
}

// ---------------- batched weight transpose -> fp16 ---------------------------
__global__ __launch_bounds__(256)
void transpose4_kernel(const float* __restrict__ W0, const float* __restrict__ W1,
                       const float* __restrict__ W2, const float* __restrict__ W3,
                       __half* __restrict__ T)
{
    __shared__ float tile[32][33];
    const int z = blockIdx.z;
    const float* W = (z == 0) ? W0 : (z == 1) ? W1 : (z == 2) ? W2 : W3;
    __half* out = T + (long)z*HID*HID;
    const int tx = threadIdx.x & 31, ty = threadIdx.x >> 5;
    const int nb = blockIdx.x * 32, kb = blockIdx.y * 32;
#pragma unroll
    for (int i = 0; i < 32; i += 8)
        tile[ty + i][tx] = W[(long)(kb + ty + i)*HID + nb + tx];
    __syncthreads();
#pragma unroll
    for (int i = 0; i < 32; i += 8)
        out[(long)(nb + ty + i)*HID + kb + tx] = __float2half_rn(tile[tx][ty + i]);
}

// ---------------- mma GEMM + bias --------------------------------------------
// C[M,N] = A[M,K] @ W[K,N] + bias; B fp16 [n][k].
// ADT 0: A fp32 (converted at frag-load time). ADT 1: A fp16 (ldmatrix).
// MODE 0: fp32 [M][N] out. MODE 1: fp16 head-split [b,h,s,d].
// CTA 128x128, 8 warps (4m x 2n), warp 32x64, k-chunk 32, 3-stage cp.async.
#define NCHUNK (HID/32)
#define BST 80                       // B smem row stride bytes
#define BBUF (128*BST)               // 10240

template<int ADT, int MODE>
__global__ __launch_bounds__(256, 2)
void gemm_mma_kernel(const void* __restrict__ Ain, const __half* __restrict__ B,
                     const float* __restrict__ bias, void* __restrict__ Cout)
{
    constexpr int AST  = (ADT == 0) ? 160 : 80;     // A smem row stride bytes
    constexpr int ABUF = 128 * AST;
    extern __shared__ char smem[];
    const uint32_t sb = smem_u32(smem);
    const uint32_t sbB = sb + 3*ABUF;
    const int t = threadIdx.x, lane = t & 31;
    const int w = t >> 5;
    const int warp_m = w & 3, warp_n = w >> 2;
    const int g = lane >> 2, tq = lane & 3;
    const int qi = lane & 7;
    const int quad_n = (lane >> 4) & 1;   // k-seg select for ldmatrix quads
    const int quad_m = (lane >> 3) & 1;   // row-half select
    const int m0 = blockIdx.y * 128, n0 = blockIdx.x * 128;

    const float*  A32 = (const float*)Ain;
    const __half* A16 = (const __half*)Ain;

    float acc[2][8][4];
#pragma unroll
    for (int mf = 0; mf < 2; mf++)
#pragma unroll
        for (int nf = 0; nf < 8; nf++)
#pragma unroll
            for (int r = 0; r < 4; r++) acc[mf][nf][r] = 0.f;

    auto issue = [&](int ck) {
        const int buf = ck % 3;
        if (ADT == 0) {
#pragma unroll
            for (int i = 0; i < 4; i++) {
                const int s = t + i*256;            // 0..1023
                const int row = s >> 3, seg = s & 7;
                CPA(sb + buf*ABUF + row*AST + seg*16,
                    A32 + (long)(m0 + row)*HID + ck*32 + seg*4);
            }
        } else {
#pragma unroll
            for (int i = 0; i < 2; i++) {
                const int s = t + i*256;            // 0..511
                const int row = s >> 2, seg = s & 3;
                CPA(sb + buf*ABUF + row*AST + seg*16,
                    A16 + (long)(m0 + row)*HID + ck*32 + seg*8);
            }
        }
#pragma unroll
        for (int i = 0; i < 2; i++) {
            const int s = t + i*256;
            const int row = s >> 2, seg = s & 3;
            CPA(sbB + buf*BBUF + row*BST + seg*16,
                B + (long)(n0 + row)*HID + ck*32 + seg*8);
        }
        CPCOMMIT();
    };

    issue(0);
    issue(1);

    for (int ck = 0; ck < NCHUNK; ck++) {
        if (ck + 1 < NCHUNK) asm volatile("cp.async.wait_group 1;" ::: "memory");
        else                 asm volatile("cp.async.wait_group 0;" ::: "memory");
        __syncthreads();
        const int buf = ck % 3;
        const uint32_t uA = sb  + buf*ABUF;
        const uint32_t uB = sbB + buf*BBUF;
#pragma unroll
        for (int ks = 0; ks < 2; ks++) {
            uint32_t a[2][4];
#pragma unroll
            for (int mf = 0; mf < 2; mf++) {
                const int mbase = warp_m*32 + mf*16;
                if (ADT == 0) {
                    const uint32_t r = uA + (mbase + g)*AST + ks*64 + tq*8;
                    float2 v0 = ldsf2(r);
                    float2 v1 = ldsf2(r + 8*AST);
                    float2 v2 = ldsf2(r + 32);
                    float2 v3 = ldsf2(r + 8*AST + 32);
                    a[mf][0] = packh2(v0.x, v0.y);
                    a[mf][1] = packh2(v1.x, v1.y);
                    a[mf][2] = packh2(v2.x, v2.y);
                    a[mf][3] = packh2(v3.x, v3.y);
                } else {
                    // x4: m0=(m0-7,k0) m1=(m8-15,k0) m2=(m0-7,k16B) m3=(m8-15,k16B)
                    const uint32_t addr = uA
                        + (mbase + quad_m*8 + qi)*AST + ks*32 + quad_n*16;
                    LDSM_X4(a[mf][0], a[mf][1], a[mf][2], a[mf][3], addr);
                }
            }
#pragma unroll
            for (int nfp = 0; nfp < 4; nfp++) {
                // x4: m0=(n0-7,k0) m1=(n0-7,k16B) m2=(n8-15,k0) m3=(n8-15,k16B)
                uint32_t b0, b1, b2, b3;
                const uint32_t addr = uB
                    + (warp_n*64 + nfp*16 + quad_m*8 + qi)*BST + ks*32 + quad_n*16;
                // note: quad layout needs (lane>>3) pairs: lanes 0-7 m0, 8-15 m1,
                // 16-23 m2, 24-31 m3 -> n-half = lane>=16, k-seg = (lane>>3)&1
                const uint32_t addr2 = uB
                    + (warp_n*64 + nfp*16 + (lane >> 4)*8 + qi)*BST
                    + ks*32 + ((lane >> 3) & 1)*16;
                (void)addr;
                LDSM_X4(b0, b1, b2, b3, addr2);
#pragma unroll
                for (int mf = 0; mf < 2; mf++) {
                    MMA_F16(acc[mf][2*nfp + 0], a[mf], b0, b1);
                    MMA_F16(acc[mf][2*nfp + 1], a[mf], b2, b3);
                }
            }
        }
        if (ck + 2 < NCHUNK) issue(ck + 2);
    }

#pragma unroll
    for (int nf = 0; nf < 8; nf++) {
        const int cb = n0 + warp_n*64 + nf*8 + 2*tq;
        const float bx = bias[cb], by = bias[cb + 1];
#pragma unroll
        for (int mf = 0; mf < 2; mf++) {
#pragma unroll
            for (int half = 0; half < 2; half++) {
                const int m = m0 + warp_m*32 + mf*16 + g + half*8;
                const float vx = acc[mf][nf][half*2 + 0] + bx;
                const float vy = acc[mf][nf][half*2 + 1] + by;
                if (MODE == 0) {
                    float2 v; v.x = vx; v.y = vy;
                    *reinterpret_cast<float2*>((float*)Cout + (long)m*HID + cb) = v;
                } else {
                    const int b = m >> 11, s = m & 2047;
                    const int h = cb >> 6, d = cb & 63;
                    *reinterpret_cast<uint32_t*>(
                        (__half*)Cout + ((long)((b*NH + h)*SS + s))*DK + d) = packh2(vx, vy);
                }
            }
        }
    }
}

#define GEMM_SMEM0 (3*128*160 + 3*BBUF)   // 92160
#define GEMM_SMEM1 (3*128*80  + 3*BBUF)   // 61440

// ---------------- flash attention on mma.sync fp16 ---------------------------
// CTA: 128 q-rows, one (b,h); 8 warps x m16. K-tile 64, 3-stage cp.async.
// Softmax in log2 domain with ex2.approx.f16x2.
#define ASTRIDE 72                    // halves per smem row (64 data + 8 pad)
#define ROWB (ASTRIDE*2)              // 144 bytes
#define QTILEB (128*ROWB)             // 18432
#define KTILEB (64*ROWB)              // 9216
#define ATT_SMEM (QTILEB + 6*KTILEB)  // 73728
#define NKT (SS/64)                   // 32 k-tiles

__global__ __launch_bounds__(256, 2)
void attn_mma_kernel(const __half* __restrict__ Qh, const __half* __restrict__ Kh,
                     const __half* __restrict__ Vh, const unsigned* __restrict__ mb,
                     __half* __restrict__ Xh)
{
    extern __shared__ char smem[];
    const uint32_t sb = smem_u32(smem);
    const int t = threadIdx.x, lane = t & 31;
    const int w = t >> 5;
    const int g = lane >> 2, tq = lane & 3;
    const int qi = lane & 7;
    const int qt = blockIdx.x, bh = blockIdx.y;
    const int b = bh >> 4, h = bh & 15;
    const int q0 = qt * 128;

    const uint32_t Qs = sb;
    const uint32_t Kbase = sb + QTILEB;
    const uint32_t Vbase = sb + QTILEB + 3*KTILEB;

    auto issueKV = [&](int kt) {
        const int buf = kt % 3;
#pragma unroll
        for (int i = 0; i < 2; i++) {
            const int s = t + i*256;                 // 0..511
            const int row = s >> 3, seg = s & 7;     // row 0..63, seg 0..7
            const uint32_t off = row*ROWB + seg*16;
            const long src = ((long)bh*SS + kt*64 + row)*DK + seg*8;
            CPA(Kbase + buf*KTILEB + off, Kh + src);
            CPA(Vbase + buf*KTILEB + off, Vh + src);
        }
        CPCOMMIT();
    };

    // Q tile: 128 rows x 8 segs = 1024 cp.asyncs (4 per thread), in group 0
#pragma unroll
    for (int i = 0; i < 4; i++) {
        const int s = t + i*256;
        const int row = s >> 3, seg = s & 7;
        CPA(Qs + row*ROWB + seg*16,
            Qh + ((long)bh*SS + q0 + row)*DK + seg*8);
    }
    issueKV(0);
    issueKV(1);

    float m_i[2] = {-1e30f, -1e30f}, l_i[2] = {0.f, 0.f};
    float O[8][4];
#pragma unroll
    for (int nf = 0; nf < 8; nf++)
#pragma unroll
        for (int r = 0; r < 4; r++) O[nf][r] = 0.f;

    uint32_t qf[4][4];
    const long mrow0 = ((long)b*SS + q0 + w*16 + g)*MW;
    const long mrow1 = mrow0 + 8L*MW;
    const float c1 = 0.1803368801111f;    // 0.125 * log2(e)

    for (int kt = 0; kt < NKT; kt++) {
        if (kt + 1 < NKT) asm volatile("cp.async.wait_group 1;" ::: "memory");
        else             asm volatile("cp.async.wait_group 0;" ::: "memory");
        __syncthreads();

        if (kt == 0) {
#pragma unroll
            for (int ks = 0; ks < 4; ks++) {
                const uint32_t addr = Qs + (w*16 + (lane & 15))*ROWB
                                    + ks*32 + (lane >> 4)*16;
                LDSM_X4(qf[ks][0], qf[ks][1], qf[ks][2], qf[ks][3], addr);
            }
        }
        const int buf = kt % 3;
        const uint32_t uK = Kbase + buf*KTILEB;
        const uint32_t uV = Vbase + buf*KTILEB;

        // ---- S = Q K^T (then scaled into log2 units)
        float S[8][4];
#pragma unroll
        for (int nfp = 0; nfp < 4; nfp++) {
#pragma unroll
            for (int r = 0; r < 4; r++) { S[2*nfp][r] = 0.f; S[2*nfp+1][r] = 0.f; }
#pragma unroll
            for (int ks = 0; ks < 4; ks++) {
                // x4: m0=(n0-7,k0) m1=(n0-7,k16B) m2=(n8-15,k0) m3=(n8-15,k16B)
                uint32_t b0, b1, b2, b3;
                const uint32_t addr = uK
                    + (nfp*16 + (lane >> 4)*8 + qi)*ROWB
                    + ks*32 + ((lane >> 3) & 1)*16;
                LDSM_X4(b0, b1, b2, b3, addr);
                MMA_F16(S[2*nfp + 0], qf[ks], b0, b1);
                MMA_F16(S[2*nfp + 1], qf[ks], b2, b3);
            }
        }
#pragma unroll
        for (int nf = 0; nf < 8; nf++)
#pragma unroll
            for (int r = 0; r < 4; r++) S[nf][r] *= c1;

        // ---- mask words
        unsigned mw0[2], mw1[2];
#pragma unroll
        for (int j = 0; j < 2; j++) {
            mw0[j] = mb[mrow0 + kt*2 + j];
            mw1[j] = mb[mrow1 + kt*2 + j];
        }

        // ---- row max (log2 units)
        float mx0 = -1e30f, mx1 = -1e30f;
#pragma unroll
        for (int nf = 0; nf < 8; nf++) {
            const int sh = ((nf & 3) << 3) + (tq << 1);
            const unsigned bt0 = (mw0[nf >> 2] >> sh) & 3u;
            const unsigned bt1 = (mw1[nf >> 2] >> sh) & 3u;
            if (bt0 & 1) mx0 = fmaxf(mx0, S[nf][0]);
            if (bt0 & 2) mx0 = fmaxf(mx0, S[nf][1]);
            if (bt1 & 1) mx1 = fmaxf(mx1, S[nf][2]);
            if (bt1 & 2) mx1 = fmaxf(mx1, S[nf][3]);
        }
#pragma unroll
        for (int off = 1; off < 4; off <<= 1) {
            mx0 = fmaxf(mx0, __shfl_xor_sync(0xffffffffu, mx0, off));
            mx1 = fmaxf(mx1, __shfl_xor_sync(0xffffffffu, mx1, off));
        }
        const float mn0 = fmaxf(m_i[0], mx0), mn1 = fmaxf(m_i[1], mx1);
        const float al0 = fex2(m_i[0] - mn0), al1 = fex2(m_i[1] - mn1);
        m_i[0] = mn0; m_i[1] = mn1;

        // ---- P = 2^(S - m) via f16x2 ex2; P frags double as PV A-operands
        float rs0 = 0.f, rs1 = 0.f;
        uint32_t pf[4][4];
#pragma unroll
        for (int nf = 0; nf < 8; nf++) {
            const int sh = ((nf & 3) << 3) + (tq << 1);
            const unsigned bt0 = (mw0[nf >> 2] >> sh) & 3u;
            const unsigned bt1 = (mw1[nf >> 2] >> sh) & 3u;
            const float a00 = (bt0 & 1) ? (S[nf][0] - mn0) : -1e4f;
            const float a01 = (bt0 & 2) ? (S[nf][1] - mn0) : -1e4f;
            const float a10 = (bt1 & 1) ? (S[nf][2] - mn1) : -1e4f;
            const float a11 = (bt1 & 2) ? (S[nf][3] - mn1) : -1e4f;
            const uint32_t p0 = h2ex2(packh2(a00, a01));
            const uint32_t p1 = h2ex2(packh2(a10, a11));
            const int ks = nf >> 1, half = (nf & 1) << 1;
            pf[ks][half + 0] = p0;
            pf[ks][half + 1] = p1;
            const float2 f0 = __half22float2(*reinterpret_cast<const __half2*>(&p0));
            const float2 f1 = __half22float2(*reinterpret_cast<const __half2*>(&p1));
            rs0 += f0.x + f0.y;
            rs1 += f1.x + f1.y;
        }
#pragma unroll
        for (int off = 1; off < 4; off <<= 1) {
            rs0 += __shfl_xor_sync(0xffffffffu, rs0, off);
            rs1 += __shfl_xor_sync(0xffffffffu, rs1, off);
        }
        l_i[0] = l_i[0]*al0 + rs0;
        l_i[1] = l_i[1]*al1 + rs1;
#pragma unroll
        for (int nf = 0; nf < 8; nf++) {
            O[nf][0] *= al0; O[nf][1] *= al0;
            O[nf][2] *= al1; O[nf][3] *= al1;
        }

        // ---- O += P V  (V via ldmatrix.x4.trans)
#pragma unroll
        for (int nfp = 0; nfp < 4; nfp++) {
#pragma unroll
            for (int ks = 0; ks < 4; ks++) {
                // x4T: m0=(k0-7,d0) m1=(k8-15,d0) m2=(k0-7,d16B) m3=(k8-15,d16B)
                uint32_t v0, v1, v2, v3;
                const uint32_t addr = uV
                    + (ks*16 + ((lane >> 3) & 1)*8 + qi)*ROWB
                    + nfp*32 + (lane >> 4)*16;
                LDSM_X4T(v0, v1, v2, v3, addr);
                MMA_F16(O[2*nfp + 0], pf[ks], v0, v1);
                MMA_F16(O[2*nfp + 1], pf[ks], v2, v3);
            }
        }
        if (kt + 2 < NKT) issueKV(kt + 2);
    }

    // ---- epilogue
    const float in0 = (l_i[0] > 0.f) ? (1.f / l_i[0]) : 0.f;
    const float in1 = (l_i[1] > 0.f) ? (1.f / l_i[1]) : 0.f;
    const long r0 = (long)(b*SS + q0 + w*16 + g);
    const long r1 = r0 + 8;
#pragma unroll
    for (int nf = 0; nf < 8; nf++) {
        const int d = h*64 + nf*8 + tq*2;
        *reinterpret_cast<uint32_t*>(Xh + r0*HID + d) = packh2(O[nf][0]*in0, O[nf][1]*in0);
        *reinterpret_cast<uint32_t*>(Xh + r1*HID + d) = packh2(O[nf][2]*in1, O[nf][3]*in1);
    }
}

// ---------------- launch -----------------------------------------------------
extern "C" void kernel_launch(void* const* d_in, const int* in_sizes, int n_in,
                              void* d_out, int out_size)
{
    const float* q    = (const float*)d_in[0];
    const float* k    = (const float*)d_in[1];
    const float* v    = (const float*)d_in[2];
    const int*   mask = (const int*)  d_in[3];
    const float* Wq   = (const float*)d_in[4];
    const float* bq   = (const float*)d_in[5];
    const float* Wk   = (const float*)d_in[6];
    const float* bk   = (const float*)d_in[7];
    const float* Wv   = (const float*)d_in[8];
    const float* bv   = (const float*)d_in[9];
    const float* Wo   = (const float*)d_in[10];
    const float* bo   = (const float*)d_in[11];
    float* out = (float*)d_out;

    __half *Qh, *Kh, *Vh, *Xh, *Wh; unsigned* mbp;
    cudaGetSymbolAddress((void**)&Qh, g_Qh);
    cudaGetSymbolAddress((void**)&Kh, g_Kh);
    cudaGetSymbolAddress((void**)&Vh, g_Vh);
    cudaGetSymbolAddress((void**)&Xh, g_Xh);
    cudaGetSymbolAddress((void**)&Wh, g_Wh);
    cudaGetSymbolAddress((void**)&mbp, g_mb);

    cudaFuncSetAttribute((const void*)gemm_mma_kernel<0,1>,
                         cudaFuncAttributeMaxDynamicSharedMemorySize, GEMM_SMEM0);
    cudaFuncSetAttribute((const void*)gemm_mma_kernel<1,0>,
                         cudaFuncAttributeMaxDynamicSharedMemorySize, GEMM_SMEM1);
    cudaFuncSetAttribute((const void*)attn_mma_kernel,
                         cudaFuncAttributeMaxDynamicSharedMemorySize, ATT_SMEM);

    pack_mask_kernel<<<(BB*SS*MW + 255)/256, 256>>>(mask, mbp);

    transpose4_kernel<<<dim3(HID/32, HID/32, 4), 256>>>(Wq, Wk, Wv, Wo, Wh);

    dim3 gg(HID/128, MM/128);
    gemm_mma_kernel<0,1><<<gg, 256, GEMM_SMEM0>>>(q, Wh + 0L*HID*HID, bq, Qh);
    gemm_mma_kernel<0,1><<<gg, 256, GEMM_SMEM0>>>(k, Wh + 1L*HID*HID, bk, Kh);
    gemm_mma_kernel<0,1><<<gg, 256, GEMM_SMEM0>>>(v, Wh + 2L*HID*HID, bv, Vh);

    attn_mma_kernel<<<dim3(SS/128, BB*NH), 256, ATT_SMEM>>>(Qh, Kh, Vh, mbp, Xh);

    gemm_mma_kernel<1,0><<<gg, 256, GEMM_SMEM1>>>(Xh, Wh + 3L*HID*HID, bo, out);
}